// round 13
// baseline (speedup 1.0000x reference)
#include <cuda_runtime.h>
#include <cuda_bf16.h>
#include <cuda_fp16.h>
#include <math.h>
#include <stdint.h>

#define BB 4
#define HS 48
#define CC 768
#define RR 192
#define NS 2304
#define NW 576
#define TOPK 3
#define NH 8
#define HD 96
#define NROW (BB*NS)
#define TROWS (BB*TOPK*4)
#define CROWS (BB*(NW-TOPK)*4)
#define VROW 9344

#define OFF_TP 0
#define SZ_TP  (BB*TOPK*4*CC)
#define OFF_XS (OFF_TP + SZ_TP)
#define SZ_XS  (NROW*CC)
#define OFF_ST (OFF_XS + SZ_XS)
#define SZ_ST  (3*TROWS*RR)
#define OFF_SC (OFF_ST + SZ_ST)

__device__ float g_zpart[BB*24*CC];
__device__ float g_zmean[BB*CC];
__device__ float g_zinv[BB];
__device__ float g_resp[BB*NS];
__device__ int   g_order[BB*NW];
__device__ int   g_msrc[VROW];
__device__ int   g_mtc[VROW];

__device__ float g_xr [(size_t)VROW*RR];
__device__ float g_kvrv[(size_t)VROW*3*RR];
__device__ float g_y  [(size_t)VROW*RR];
__device__ float g_tcv[(size_t)NROW*CC];

__device__ __nv_bfloat16 g_xq_b[(size_t)NROW*CC];
__device__ __nv_bfloat16 g_f_b [(size_t)NROW*CC];
__device__ __nv_bfloat16 g_q_b [(size_t)NROW*CC];
__device__ __nv_bfloat16 g_k_b [(size_t)NROW*CC];
__device__ __half        g_v_h [(size_t)NROW*CC];
__device__ __nv_bfloat16 g_o_b [(size_t)NROW*CC];
__device__ __nv_bfloat16 g_wqkv_b[3*CC*CC];
__device__ __nv_bfloat16 g_wout_b[CC*CC];

__device__ __nv_bfloat16 g_wd_h[2*RR*CC],    g_wd_l[2*RR*CC];
__device__ __nv_bfloat16 g_kvr_h[2*3*RR*RR], g_kvr_l[2*3*RR*RR];
__device__ __nv_bfloat16 g_wup_h[CC*RR],     g_wup_l[CC*RR];
__device__ __nv_bfloat16 g_wc_h[2*CC*RR],    g_wc_l[2*CC*RR];   // Wup@wo per expert

// ------- helpers -------
__device__ __forceinline__ uint32_t smaddr(const void* p) {
    return (uint32_t)__cvta_generic_to_shared(p);
}
__device__ __forceinline__ void ldsm4(uint32_t* r, uint32_t a) {
    asm volatile("ldmatrix.sync.aligned.m8n8.x4.shared.b16 {%0,%1,%2,%3}, [%4];"
        : "=r"(r[0]), "=r"(r[1]), "=r"(r[2]), "=r"(r[3]) : "r"(a));
}
__device__ __forceinline__ void ldsm4t(uint32_t* r, uint32_t a) {
    asm volatile("ldmatrix.sync.aligned.m8n8.x4.trans.shared.b16 {%0,%1,%2,%3}, [%4];"
        : "=r"(r[0]), "=r"(r[1]), "=r"(r[2]), "=r"(r[3]) : "r"(a));
}
__device__ __forceinline__ void mma16816(float* d, const uint32_t* a, uint32_t b0, uint32_t b1) {
    asm volatile("mma.sync.aligned.m16n8k16.row.col.f32.bf16.bf16.f32 "
        "{%0,%1,%2,%3}, {%4,%5,%6,%7}, {%8,%9}, {%0,%1,%2,%3};"
        : "+f"(d[0]), "+f"(d[1]), "+f"(d[2]), "+f"(d[3])
        : "r"(a[0]), "r"(a[1]), "r"(a[2]), "r"(a[3]), "r"(b0), "r"(b1));
}
__device__ __forceinline__ void mma16816h(float* d, const uint32_t* a, uint32_t b0, uint32_t b1) {
    asm volatile("mma.sync.aligned.m16n8k16.row.col.f32.f16.f16.f32 "
        "{%0,%1,%2,%3}, {%4,%5,%6,%7}, {%8,%9}, {%0,%1,%2,%3};"
        : "+f"(d[0]), "+f"(d[1]), "+f"(d[2]), "+f"(d[3])
        : "r"(a[0]), "r"(a[1]), "r"(a[2]), "r"(a[3]), "r"(b0), "r"(b1));
}
__device__ __forceinline__ float ex2f(float x) {
    float y; asm("ex2.approx.f32 %0, %1;" : "=f"(y) : "f"(x)); return y;
}
__device__ __forceinline__ uint32_t h2ex2(uint32_t x) {
    uint32_t y; asm("ex2.approx.f16x2 %0, %1;" : "=r"(y) : "r"(x)); return y;
}
__device__ __forceinline__ uint32_t hadd2u(uint32_t a, uint32_t b) {
    uint32_t y; asm("add.rn.f16x2 %0, %1, %2;" : "=r"(y) : "r"(a), "r"(b)); return y;
}
__device__ __forceinline__ uint32_t packbf(float a, float b) {
    __nv_bfloat162 t = __floats2bfloat162_rn(a, b);
    return *reinterpret_cast<uint32_t*>(&t);
}
__device__ __forceinline__ uint32_t packh(float a, float b) {
    __half2 t = __floats2half2_rn(a, b);
    return *reinterpret_cast<uint32_t*>(&t);
}

// ---- K1a ----
__global__ __launch_bounds__(CC) void k_zpart(const float* __restrict__ xz) {
    int b = blockIdx.x / 24, chunk = blockIdx.x % 24;
    int c = threadIdx.x;
    const float* p = xz + ((size_t)b*NS + (size_t)chunk*96)*CC + c;
    float s = 0.f;
    #pragma unroll 4
    for (int n = 0; n < 96; n++) s += p[(size_t)n*CC];
    g_zpart[(b*24 + chunk)*CC + c] = s;
}

// ---- K1b ----
__global__ __launch_bounds__(CC) void k_zfin() {
    __shared__ float red[CC];
    int b = blockIdx.x, c = threadIdx.x;
    float s = 0.f;
    for (int j = 0; j < 24; j++) s += g_zpart[(b*24 + j)*CC + c];
    float zm = s * (1.f/NS);
    g_zmean[b*CC + c] = zm;
    red[c] = zm*zm;
    __syncthreads();
    for (int st = 512; st > 0; st >>= 1) {
        if (c < st && c + st < CC) red[c] += red[c+st];
        __syncthreads();
    }
    if (c == 0) g_zinv[b] = 1.f / fmaxf(sqrtf(red[0]), 1e-12f);
}

// ---- K2: resp ----
__global__ __launch_bounds__(256) void k_resp(const float* __restrict__ xs) {
    int row = blockIdx.x;
    int b = row / NS;
    const float* x = xs + (size_t)row*CC;
    const float* z = g_zmean + b*CC;
    float d = 0.f, xx = 0.f;
    for (int c = threadIdx.x; c < CC; c += 256) {
        float xv = x[c];
        d += xv * z[c];
        xx += xv * xv;
    }
    __shared__ float sd[8], sx2[8];
    int lane = threadIdx.x & 31, wid = threadIdx.x >> 5;
    for (int o = 16; o; o >>= 1) {
        d  += __shfl_down_sync(0xffffffffu, d, o);
        xx += __shfl_down_sync(0xffffffffu, xx, o);
    }
    if (lane == 0) { sd[wid] = d; sx2[wid] = xx; }
    __syncthreads();
    if (threadIdx.x == 0) {
        float D = 0.f, X = 0.f;
        for (int i = 0; i < 8; i++) { D += sd[i]; X += sx2[i]; }
        g_resp[row] = D * g_zinv[b] / fmaxf(sqrtf(X), 1e-12f);
    }
}

// ---- K3: window rank ----
__global__ __launch_bounds__(NW) void k_order() {
    __shared__ __align__(16) float wm[NW];
    int b = blockIdx.x, w = threadIdx.x;
    int wi = w / 24, wj = w % 24;
    int base = b*NS + (2*wi)*HS + 2*wj;
    float v = 0.25f*(g_resp[base] + g_resp[base+1] + g_resp[base+HS] + g_resp[base+HS+1]);
    wm[w] = v;
    __syncthreads();
    int rank = 0;
    const float4* wm4 = reinterpret_cast<const float4*>(wm);
    for (int j = 0; j < NW/4; j++) {
        float4 u = wm4[j];
        int j4 = 4*j;
        rank += (u.x > v || (u.x == v && j4   < w));
        rank += (u.y > v || (u.y == v && j4+1 < w));
        rank += (u.z > v || (u.z == v && j4+2 < w));
        rank += (u.w > v || (u.w == v && j4+3 < w));
    }
    g_order[b*NW + rank] = w;
}

// ---- prep ----
__global__ __launch_bounds__(256) void k_prep() {
    int vr = blockIdx.x*256 + threadIdx.x;
    if (vr >= VROW) return;
    int src = 0, tc = 0;
    bool valid = (vr < 48) || (vr >= 128 && vr < 9296);
    if (valid) {
        int b, p, t;
        if (vr < 48) { b = vr/12; int m = vr%12; p = m>>2; t = m&3; tc = b*NS + m; }
        else { int rp = vr-128; b = rp/2292; int mm = rp%2292; p = TOPK + (mm>>2); t = mm&3; tc = b*NS + 12 + mm; }
        int w = g_order[b*NW + p];
        int wi = w / 24, wj = w % 24;
        src = b*NS + (2*wi + (t>>1))*HS + 2*wj + (t&1);
    }
    g_msrc[vr] = src;
    g_mtc[vr]  = tc;
}

// ---- weight split ----
__global__ __launch_bounds__(256) void k_wsplit(
    const float* __restrict__ Wdo_w, const float* __restrict__ Wdc_w,
    const float* __restrict__ te_k, const float* __restrict__ te_v, const float* __restrict__ te_r,
    const float* __restrict__ ce_k, const float* __restrict__ ce_v, const float* __restrict__ ce_r,
    const float* __restrict__ Wup_w)
{
    int i = blockIdx.x*256 + threadIdx.x;
    const int WD = RR*CC;
    const int WS = RR*RR;
    float v; __nv_bfloat16* hp; __nv_bfloat16* lp; int o;
    if      (i < WD)            { v = Wdo_w[i];        hp = g_wd_h;  lp = g_wd_l;  o = i; }
    else if (i < 2*WD)          { v = Wdc_w[i-WD];     hp = g_wd_h;  lp = g_wd_l;  o = i; }
    else if (i < 2*WD + WS)     { v = te_k[i-2*WD];          hp = g_kvr_h; lp = g_kvr_l; o = i-2*WD; }
    else if (i < 2*WD + 2*WS)   { v = te_v[i-2*WD-WS];       hp = g_kvr_h; lp = g_kvr_l; o = i-2*WD; }
    else if (i < 2*WD + 3*WS)   { v = te_r[i-2*WD-2*WS];     hp = g_kvr_h; lp = g_kvr_l; o = i-2*WD; }
    else if (i < 2*WD + 4*WS)   { v = ce_k[i-2*WD-3*WS];     hp = g_kvr_h; lp = g_kvr_l; o = i-2*WD; }
    else if (i < 2*WD + 5*WS)   { v = ce_v[i-2*WD-4*WS];     hp = g_kvr_h; lp = g_kvr_l; o = i-2*WD; }
    else if (i < 2*WD + 6*WS)   { v = ce_r[i-2*WD-5*WS];     hp = g_kvr_h; lp = g_kvr_l; o = i-2*WD; }
    else if (i < 3*WD + 6*WS)   { v = Wup_w[i-2*WD-6*WS];    hp = g_wup_h; lp = g_wup_l; o = i-2*WD-6*WS; }
    else return;
    __nv_bfloat16 h = __float2bfloat16_rn(v);
    hp[o] = h;
    lp[o] = __float2bfloat16_rn(v - __bfloat162float(h));
}

// ---- Wcomb = Wup @ wo_e  (768x192 per expert), split to bf16 hi/lo ----
__global__ __launch_bounds__(RR) void k_wcomb(
    const float* __restrict__ Wup, const float* __restrict__ te_o, const float* __restrict__ ce_o)
{
    __shared__ float sw[16][RR];
    int e = blockIdx.y;
    int c0 = blockIdx.x * 16;
    int r = threadIdx.x;
    const float* wo = e ? ce_o : te_o;
    for (int i = r; i < 16*RR; i += RR)
        sw[i/RR][i%RR] = Wup[(size_t)(c0 + i/RR)*RR + (i%RR)];
    __syncthreads();
    #pragma unroll 1
    for (int c = 0; c < 16; c++) {
        float acc = 0.f;
        #pragma unroll 4
        for (int n = 0; n < RR; n++) acc += sw[c][n] * wo[n*RR + r];
        size_t p = ((size_t)e*CC + c0 + c)*RR + r;
        __nv_bfloat16 h = __float2bfloat16_rn(acc);
        g_wc_h[p] = h;
        g_wc_l[p] = __float2bfloat16_rn(acc - __bfloat162float(h));
    }
}

// ---- split-precision tensor GEMM (RWKV chain) ----
#define GSTR 40
__global__ __launch_bounds__(256) void k_gemm3(
    const float* __restrict__ A, int lda, int K,
    const __nv_bfloat16* __restrict__ Bh0, const __nv_bfloat16* __restrict__ Bl0,
    const __nv_bfloat16* __restrict__ Bh1, const __nv_bfloat16* __restrict__ Bl1,
    const float* __restrict__ bias0, const float* __restrict__ bias1,
    float* __restrict__ C, int ldc, int mode, float* __restrict__ out)
{
    __shared__ __nv_bfloat16 Ah[128*GSTR], Al[128*GSTR];
    __shared__ __nv_bfloat16 Bhs[64*GSTR], Bls[64*GSTR];
    int m0 = blockIdx.x * 128, n0 = blockIdx.y * 64;
    bool e0 = (blockIdx.x == 0);
    const __nv_bfloat16* Bhp = e0 ? Bh0 : Bh1;
    const __nv_bfloat16* Blp = e0 ? Bl0 : Bl1;
    const float* bias = e0 ? bias0 : bias1;
    int tid = threadIdx.x, l = tid & 31, w = tid >> 5;
    int mw = (w >> 1) * 32, nw = (w & 1) * 32;
    int ar = tid >> 1, ac = (tid & 1) * 16;
    int br = tid >> 2, bc = (tid & 3) * 8;

    const float* Arow = A + (size_t)((mode == 0) ? g_msrc[m0+ar] : (m0+ar))*lda;

    float acc[2][4][4];
    #pragma unroll
    for (int mi = 0; mi < 2; mi++)
        #pragma unroll
        for (int nj = 0; nj < 4; nj++)
            #pragma unroll
            for (int q = 0; q < 4; q++) acc[mi][nj][q] = 0.f;

    float4 fa[4]; uint4 rbh, rbl;
    #pragma unroll
    for (int j = 0; j < 4; j++) fa[j] = *reinterpret_cast<const float4*>(Arow + ac + 4*j);
    rbh = *reinterpret_cast<const uint4*>(Bhp + (size_t)(n0+br)*K + bc);
    rbl = *reinterpret_cast<const uint4*>(Blp + (size_t)(n0+br)*K + bc);

    int g = l >> 3, lg = l & 7;
    uint32_t aoff = (uint32_t)(((mw + (l & 15))*GSTR + ((l >> 4) << 3)) * 2);
    uint32_t ah_base = smaddr(Ah) + aoff;
    uint32_t al_base = smaddr(Al) + aoff;
    uint32_t boff = (uint32_t)(((nw + ((g & 2) ? 8 : 0) + lg)*GSTR + ((g & 1) ? 8 : 0)) * 2);
    uint32_t bh_base = smaddr(Bhs) + boff;
    uint32_t bl_base = smaddr(Bls) + boff;

    for (int kc = 0; kc < K; kc += 32) {
        #pragma unroll
        for (int j = 0; j < 4; j++) {
            float vals[4] = {fa[j].x, fa[j].y, fa[j].z, fa[j].w};
            #pragma unroll
            for (int e = 0; e < 4; e += 2) {
                float v0 = vals[e], v1 = vals[e+1];
                uint32_t hp = packbf(v0, v1);
                __nv_bfloat162 hh = *reinterpret_cast<__nv_bfloat162*>(&hp);
                float l0 = v0 - __bfloat162float(hh.x);
                float l1 = v1 - __bfloat162float(hh.y);
                int col = ac + 4*j + e;
                *reinterpret_cast<uint32_t*>(&Ah[ar*GSTR + col]) = hp;
                *reinterpret_cast<uint32_t*>(&Al[ar*GSTR + col]) = packbf(l0, l1);
            }
        }
        *reinterpret_cast<uint4*>(&Bhs[br*GSTR + bc]) = rbh;
        *reinterpret_cast<uint4*>(&Bls[br*GSTR + bc]) = rbl;
        __syncthreads();
        if (kc + 32 < K) {
            #pragma unroll
            for (int j = 0; j < 4; j++)
                fa[j] = *reinterpret_cast<const float4*>(Arow + kc + 32 + ac + 4*j);
            rbh = *reinterpret_cast<const uint4*>(Bhp + (size_t)(n0+br)*K + kc + 32 + bc);
            rbl = *reinterpret_cast<const uint4*>(Blp + (size_t)(n0+br)*K + kc + 32 + bc);
        }
        #pragma unroll
        for (int kk = 0; kk < 2; kk++) {
            uint32_t ah[2][4], alr[2][4];
            ldsm4(ah[0],  ah_base + (kk*16)*2);
            ldsm4(ah[1],  ah_base + (16*GSTR + kk*16)*2);
            ldsm4(alr[0], al_base + (kk*16)*2);
            ldsm4(alr[1], al_base + (16*GSTR + kk*16)*2);
            #pragma unroll
            for (int np = 0; np < 2; np++) {
                uint32_t bh[4], bl2[4];
                ldsm4(bh,  bh_base + (np*16*GSTR + kk*16)*2);
                ldsm4(bl2, bl_base + (np*16*GSTR + kk*16)*2);
                #pragma unroll
                for (int mi = 0; mi < 2; mi++) {
                    mma16816(acc[mi][2*np],   ah[mi],  bh[0],  bh[1]);
                    mma16816(acc[mi][2*np],   ah[mi],  bl2[0], bl2[1]);
                    mma16816(acc[mi][2*np],   alr[mi], bh[0],  bh[1]);
                    mma16816(acc[mi][2*np+1], ah[mi],  bh[2],  bh[3]);
                    mma16816(acc[mi][2*np+1], ah[mi],  bl2[2], bl2[3]);
                    mma16816(acc[mi][2*np+1], alr[mi], bh[2],  bh[3]);
                }
            }
        }
        __syncthreads();
    }

    #pragma unroll
    for (int mi = 0; mi < 2; mi++) {
        int row_lo = m0 + mw + mi*16 + (l >> 2);
        #pragma unroll
        for (int nj = 0; nj < 4; nj++) {
            int col = n0 + nw + nj*8 + (l & 3)*2;
            float b0 = bias ? bias[col]   : 0.f;
            float b1 = bias ? bias[col+1] : 0.f;
            float c0 = acc[mi][nj][0] + b0, c1 = acc[mi][nj][1] + b1;
            float c2 = acc[mi][nj][2] + b0, c3 = acc[mi][nj][3] + b1;
            if (mode < 2) {
                size_t plo = (size_t)row_lo*ldc + col;
                size_t phi = (size_t)(row_lo+8)*ldc + col;
                C[plo] = c0; C[plo+1] = c1;
                C[phi] = c2; C[phi+1] = c3;
            } else {
                int vr0 = row_lo, vr1 = row_lo + 8;
                if (vr0 < 48 || (vr0 >= 128 && vr0 < 9296)) {
                    size_t p = (size_t)g_mtc[vr0]*CC + col;
                    C[p] = c0; C[p+1] = c1;
                    if (vr0 < 48) { out[OFF_TP + (size_t)vr0*CC + col] = c0; out[OFF_TP + (size_t)vr0*CC + col + 1] = c1; }
                }
                if (vr1 < 48 || (vr1 >= 128 && vr1 < 9296)) {
                    size_t p = (size_t)g_mtc[vr1]*CC + col;
                    C[p] = c2; C[p+1] = c3;
                    if (vr1 < 48) { out[OFF_TP + (size_t)vr1*CC + col] = c2; out[OFF_TP + (size_t)vr1*CC + col + 1] = c3; }
                }
            }
        }
    }
}

// ---- pointwise RWKV state update ----
__global__ __launch_bounds__(RR) void k_point(
    const float* __restrict__ state_t, const float* __restrict__ state_c,
    const float* __restrict__ te_td, const float* __restrict__ te_tf,
    const float* __restrict__ ce_td, const float* __restrict__ ce_tf,
    float* __restrict__ out)
{
    int n = threadIdx.x;
    int vr0 = blockIdx.x * 8;
    #pragma unroll
    for (int i = 0; i < 8; i++) {
        int vr = vr0 + i;
        bool top = (vr < 48);
        if (!top && (vr < 128 || vr >= 9296)) continue;
        const float* st = top ? state_t : state_c;
        int srow = top ? vr : vr - 128;
        size_t nplane = top ? (size_t)TROWS*RR : (size_t)CROWS*RR;
        float* ost = out + (top ? OFF_ST : OFF_SC);

        float kk = g_kvrv[(size_t)vr*(3*RR) + n];
        float vv = g_kvrv[(size_t)vr*(3*RR) + RR + n];
        float rr = g_kvrv[(size_t)vr*(3*RR) + 2*RR + n];
        float td = (top ? te_td : ce_td)[n];
        float tf = (top ? te_tf : ce_tf)[n];
        float wexp = expf(td);

        float rv = 1.f / (1.f + expf(-rr));
        size_t base = (size_t)srow*RR + n;
        float aa = st[base], bb = st[nplane + base], pp = st[2*nplane + base];
        float ww = tf + kk;
        float pm = fmaxf(pp, ww);
        float e1 = expf(pp - pm), e2 = expf(ww - pm);
        float wkv = (e1*aa + e2*vv) / (e1*bb + e2);
        float ww2 = pp - wexp;
        float p2 = fmaxf(ww2, kk);
        float f1 = expf(ww2 - p2), f2 = expf(kk - p2);
        ost[base]            = f1*aa + f2*vv;
        ost[nplane + base]   = f1*bb + f2;
        ost[2*nplane + base] = p2;
        g_y[(size_t)vr*RR + n] = rv * wkv;
    }
}

// ---- K5: LN (both rows per block) ----
__global__ __launch_bounds__(256) void k_ln(const float* __restrict__ xs,
    const float* __restrict__ qn_g, const float* __restrict__ qn_b,
    const float* __restrict__ fn_g, const float* __restrict__ fn_b)
{
    __shared__ float row[CC];
    __shared__ float warpred[8];
    __shared__ float stat[2];
    int r = blockIdx.x;
    int tid = threadIdx.x, lane = tid & 31, wid = tid >> 5;

    #pragma unroll 1
    for (int isf = 0; isf < 2; isf++) {
        const float* src = isf ? g_tcv + (size_t)r*CC : xs + (size_t)r*CC;
        __nv_bfloat16* dst = isf ? g_f_b + (size_t)r*CC : g_xq_b + (size_t)r*CC;
        const float* gg = isf ? fn_g : qn_g;
        const float* bb = isf ? fn_b : qn_b;

        float s = 0.f;
        for (int c = tid; c < CC; c += 256) { float v = src[c]; row[c] = v; s += v; }
        for (int o = 16; o; o >>= 1) s += __shfl_down_sync(0xffffffffu, s, o);
        if (lane == 0) warpred[wid] = s;
        __syncthreads();
        if (tid == 0) { float t = 0.f; for (int i = 0; i < 8; i++) t += warpred[i]; stat[0] = t * (1.f/CC); }
        __syncthreads();
        float m = stat[0], vs = 0.f;
        for (int c = tid; c < CC; c += 256) { float d = row[c] - m; vs += d*d; }
        for (int o = 16; o; o >>= 1) vs += __shfl_down_sync(0xffffffffu, vs, o);
        if (lane == 0) warpred[wid] = vs;
        __syncthreads();
        if (tid == 0) { float t = 0.f; for (int i = 0; i < 8; i++) t += warpred[i]; stat[1] = rsqrtf(t*(1.f/CC) + 1e-6f); }
        __syncthreads();
        float inv = stat[1];
        for (int c = tid; c < CC; c += 256)
            dst[c] = __float2bfloat16_rn((row[c] - m) * inv * gg[c] + bb[c]);
        __syncthreads();
    }
}

// ---- attention weight convert ----
__global__ __launch_bounds__(256) void k_wconv(const float* __restrict__ win,
                                              const float* __restrict__ wout) {
    int i = blockIdx.x*256 + threadIdx.x;
    int p = i*2;
    if (p < 3*CC*CC) {
        *reinterpret_cast<uint32_t*>(&g_wqkv_b[p]) = packbf(win[p], win[p+1]);
    }
    if (p < CC*CC) {
        *reinterpret_cast<uint32_t*>(&g_wout_b[p]) = packbf(wout[p], wout[p+1]);
    }
}

// ---- K6: bf16 tensor-core GEMM 128x64 ----
#define ASTR 40
__global__ __launch_bounds__(256) void k_gemm_bf(
    const __nv_bfloat16* __restrict__ A, const __nv_bfloat16* __restrict__ W,
    const float* __restrict__ bias, __nv_bfloat16* __restrict__ dstb,
    float* __restrict__ dstf, const float* __restrict__ xs,
    const float* __restrict__ router, int mode)
{
    __shared__ __nv_bfloat16 As[128*ASTR];
    __shared__ __nv_bfloat16 Bs[64*ASTR];
    int m0 = blockIdx.x * 128, n0 = blockIdx.y * 64;
    int tid = threadIdx.x;
    int l = tid & 31, w = tid >> 5;
    int mw = (w >> 1) * 32, nw = (w & 1) * 32;
    int ldr = tid >> 2, ldc = (tid & 3) * 8;

    float acc[2][4][4];
    #pragma unroll
    for (int mi = 0; mi < 2; mi++)
        #pragma unroll
        for (int nj = 0; nj < 4; nj++)
            #pragma unroll
            for (int q = 0; q < 4; q++) acc[mi][nj][q] = 0.f;

    uint4 ra0, ra1, rb;
    ra0 = *reinterpret_cast<const uint4*>(A + (size_t)(m0+ldr)*CC + ldc);
    ra1 = *reinterpret_cast<const uint4*>(A + (size_t)(m0+64+ldr)*CC + ldc);
    rb  = *reinterpret_cast<const uint4*>(W + (size_t)(n0+ldr)*CC + ldc);

    int g = l >> 3, lg = l & 7;
    uint32_t a_base = smaddr(As) + (uint32_t)(((mw + (l & 15))*ASTR + ((l >> 4) << 3)) * 2);
    uint32_t b_base = smaddr(Bs) + (uint32_t)(((nw + ((g & 2) ? 8 : 0) + lg)*ASTR + ((g & 1) ? 8 : 0)) * 2);

    for (int kc = 0; kc < CC; kc += 32) {
        *reinterpret_cast<uint4*>(&As[ldr*ASTR + ldc])      = ra0;
        *reinterpret_cast<uint4*>(&As[(64+ldr)*ASTR + ldc]) = ra1;
        *reinterpret_cast<uint4*>(&Bs[ldr*ASTR + ldc])      = rb;
        __syncthreads();
        if (kc + 32 < CC) {
            ra0 = *reinterpret_cast<const uint4*>(A + (size_t)(m0+ldr)*CC + kc + 32 + ldc);
            ra1 = *reinterpret_cast<const uint4*>(A + (size_t)(m0+64+ldr)*CC + kc + 32 + ldc);
            rb  = *reinterpret_cast<const uint4*>(W + (size_t)(n0+ldr)*CC + kc + 32 + ldc);
        }
        #pragma unroll
        for (int kk = 0; kk < 2; kk++) {
            uint32_t af[2][4];
            ldsm4(af[0], a_base + (kk*16)*2);
            ldsm4(af[1], a_base + (16*ASTR + kk*16)*2);
            #pragma unroll
            for (int np = 0; np < 2; np++) {
                uint32_t bf[4];
                ldsm4(bf, b_base + (np*16*ASTR + kk*16)*2);
                #pragma unroll
                for (int mi = 0; mi < 2; mi++) {
                    mma16816(acc[mi][2*np],   af[mi], bf[0], bf[1]);
                    mma16816(acc[mi][2*np+1], af[mi], bf[2], bf[3]);
                }
            }
        }
        __syncthreads();
    }

    #pragma unroll
    for (int mi = 0; mi < 2; mi++) {
        int row_lo = m0 + mw + mi*16 + (l >> 2);
        #pragma unroll
        for (int nj = 0; nj < 4; nj++) {
            int col = n0 + nw + nj*8 + (l & 3)*2;
            float b0 = bias[col], b1 = bias[col+1];
            float c0 = acc[mi][nj][0] + b0, c1 = acc[mi][nj][1] + b1;
            float c2 = acc[mi][nj][2] + b0, c3 = acc[mi][nj][3] + b1;
            size_t plo = (size_t)row_lo*CC + col;
            size_t phi = (size_t)(row_lo+8)*CC + col;
            if (mode == 0) {
                *reinterpret_cast<uint32_t*>(&dstb[plo]) = packbf(c0, c1);
                *reinterpret_cast<uint32_t*>(&dstb[phi]) = packbf(c2, c3);
            } else if (mode == 3) {
                __half* dh = reinterpret_cast<__half*>(dstb);
                *reinterpret_cast<uint32_t*>(&dh[plo]) = packh(c0, c1);
                *reinterpret_cast<uint32_t*>(&dh[phi]) = packh(c2, c3);
            } else {
                float r0 = router[col], r1 = router[col+1];
                dstf[plo]   = xs[plo]   + r0*c0;
                dstf[plo+1] = xs[plo+1] + r1*c1;
                dstf[phi]   = xs[phi]   + r0*c2;
                dstf[phi+1] = xs[phi+1] + r1*c3;
            }
        }
    }
}

// ---- K7: flash attention (R11 proven version: register-staged KV prefetch) ----
#define QSTR 104
#define FL_Q 0
#define FL_K (128*QSTR)
#define FL_V (FL_K + 64*QSTR)
#define FL_SMEM ((FL_V + 64*QSTR)*2)

__global__ __launch_bounds__(256) void k_flash_bf() {
    extern __shared__ __align__(16) __nv_bfloat16 fsm[];
    __nv_bfloat16* Qs = fsm + FL_Q;
    __nv_bfloat16* Ks = fsm + FL_K;
    __nv_bfloat16* Vs = fsm + FL_V;   // holds __half data

    int blk = blockIdx.x;
    int qt = blk % 18;
    int h  = (blk / 18) % NH;
    int b  = blk / (18*NH);
    int q0 = qt * 128;
    int tid = threadIdx.x;
    int l = tid & 31, w = tid >> 5;
    int g = l >> 3, lg = l & 7;
    const float sc2 = 0.14725602686637387f;  // log2(e)/sqrt(96)

    for (int i = tid; i < 128*12; i += 256) {
        int r = i / 12, j = i % 12;
        *reinterpret_cast<uint4*>(&Qs[r*QSTR + j*8]) =
            *reinterpret_cast<const uint4*>(&g_q_b[(size_t)(b*NS + q0 + r)*CC + h*HD + j*8]);
    }

    float Oacc[12][4];
    float m_lo = -1e30f, m_hi = -1e30f, l_lo = 0.f, l_hi = 0.f;
    #pragma unroll
    for (int t = 0; t < 12; t++)
        #pragma unroll
        for (int q = 0; q < 4; q++) Oacc[t][q] = 0.f;

    uint32_t q_base = smaddr(Qs) + (uint32_t)(((w*16 + (l & 15))*QSTR + ((l >> 4) << 3)) * 2);
    uint32_t k_base = smaddr(Ks) + (uint32_t)((((g & 2) ? 8 : 0) + lg)*QSTR + ((g & 1) ? 8 : 0)) * 2;
    uint32_t v_base = smaddr(Vs) + (uint32_t)((((g & 1) ? 8 : 0) + lg)*QSTR + ((g & 2) ? 8 : 0)) * 2;

    uint4 kr[3], vr[3];
    #pragma unroll
    for (int c = 0; c < 3; c++) {
        int i = tid + c*256;
        int r = i / 12, j = i % 12;
        kr[c] = *reinterpret_cast<const uint4*>(&g_k_b[(size_t)(b*NS + r)*CC + h*HD + j*8]);
        vr[c] = *reinterpret_cast<const uint4*>(&g_v_h[(size_t)(b*NS + r)*CC + h*HD + j*8]);
    }

    for (int kt = 0; kt < 36; kt++) {
        __syncthreads();
        #pragma unroll
        for (int c = 0; c < 3; c++) {
            int i = tid + c*256;
            int r = i / 12, j = i % 12;
            *reinterpret_cast<uint4*>(&Ks[r*QSTR + j*8]) = kr[c];
            *reinterpret_cast<uint4*>(&Vs[r*QSTR + j*8]) = vr[c];
        }
        __syncthreads();
        if (kt + 1 < 36) {
            int k0n = (kt + 1) * 64;
            #pragma unroll
            for (int c = 0; c < 3; c++) {
                int i = tid + c*256;
                int r = i / 12, j = i % 12;
                kr[c] = *reinterpret_cast<const uint4*>(&g_k_b[(size_t)(b*NS + k0n + r)*CC + h*HD + j*8]);
                vr[c] = *reinterpret_cast<const uint4*>(&g_v_h[(size_t)(b*NS + k0n + r)*CC + h*HD + j*8]);
            }
        }

        // S = Q @ K^T (bf16)
        float sacc[8][4];
        #pragma unroll
        for (int j = 0; j < 8; j++)
            #pragma unroll
            for (int q = 0; q < 4; q++) sacc[j][q] = 0.f;
        #pragma unroll
        for (int d = 0; d < 6; d++) {
            uint32_t af[4];
            ldsm4(af, q_base + (d*16)*2);
            #pragma unroll
            for (int np = 0; np < 4; np++) {
                uint32_t bf[4];
                ldsm4(bf, k_base + (np*16*QSTR + d*16)*2);
                mma16816(sacc[2*np],   af, bf[0], bf[1]);
                mma16816(sacc[2*np+1], af, bf[2], bf[3]);
            }
        }

        // online softmax: max in fp32, exp via ex2.approx.f16x2
        float mx_lo = -1e30f, mx_hi = -1e30f;
        #pragma unroll
        for (int j = 0; j < 8; j++) {
            mx_lo = fmaxf(mx_lo, fmaxf(sacc[j][0], sacc[j][1]));
            mx_hi = fmaxf(mx_hi, fmaxf(sacc[j][2], sacc[j][3]));
        }
        mx_lo *= sc2; mx_hi *= sc2;
        mx_lo = fmaxf(mx_lo, __shfl_xor_sync(0xffffffffu, mx_lo, 1));
        mx_lo = fmaxf(mx_lo, __shfl_xor_sync(0xffffffffu, mx_lo, 2));
        mx_hi = fmaxf(mx_hi, __shfl_xor_sync(0xffffffffu, mx_hi, 1));
        mx_hi = fmaxf(mx_hi, __shfl_xor_sync(0xffffffffu, mx_hi, 2));
        float mn_lo = fmaxf(m_lo, mx_lo), mn_hi = fmaxf(m_hi, mx_hi);
        float al_lo = ex2f(m_lo - mn_lo), al_hi = ex2f(m_hi - mn_hi);

        uint32_t ph[8][2];
        #pragma unroll
        for (int j = 0; j < 8; j++) {
            float x0 = fmaf(sacc[j][0], sc2, -mn_lo);
            float x1 = fmaf(sacc[j][1], sc2, -mn_lo);
            float x2 = fmaf(sacc[j][2], sc2, -mn_hi);
            float x3 = fmaf(sacc[j][3], sc2, -mn_hi);
            ph[j][0] = h2ex2(packh(x0, x1));
            ph[j][1] = h2ex2(packh(x2, x3));
        }
        uint32_t slo = hadd2u(hadd2u(hadd2u(ph[0][0], ph[1][0]), hadd2u(ph[2][0], ph[3][0])),
                              hadd2u(hadd2u(ph[4][0], ph[5][0]), hadd2u(ph[6][0], ph[7][0])));
        uint32_t shi = hadd2u(hadd2u(hadd2u(ph[0][1], ph[1][1]), hadd2u(ph[2][1], ph[3][1])),
                              hadd2u(hadd2u(ph[4][1], ph[5][1]), hadd2u(ph[6][1], ph[7][1])));
        __half2 hlo = *reinterpret_cast<__half2*>(&slo);
        __half2 hhi = *reinterpret_cast<__half2*>(&shi);
        float rs_lo = __low2float(hlo) + __high2float(hlo);
        float rs_hi = __low2float(hhi) + __high2float(hhi);
        rs_lo += __shfl_xor_sync(0xffffffffu, rs_lo, 1);
        rs_lo += __shfl_xor_sync(0xffffffffu, rs_lo, 2);
        rs_hi += __shfl_xor_sync(0xffffffffu, rs_hi, 1);
        rs_hi += __shfl_xor_sync(0xffffffffu, rs_hi, 2);
        l_lo = l_lo*al_lo + rs_lo;
        l_hi = l_hi*al_hi + rs_hi;
        m_lo = mn_lo; m_hi = mn_hi;
        #pragma unroll
        for (int t = 0; t < 12; t++) {
            Oacc[t][0] *= al_lo; Oacc[t][1] *= al_lo;
            Oacc[t][2] *= al_hi; Oacc[t][3] *= al_hi;
        }

        // P @ V in fp16
        #pragma unroll
        for (int kt2 = 0; kt2 < 4; kt2++) {
            uint32_t pf[4];
            pf[0] = ph[2*kt2][0];
            pf[1] = ph[2*kt2][1];
            pf[2] = ph[2*kt2+1][0];
            pf[3] = ph[2*kt2+1][1];
            #pragma unroll
            for (int dp = 0; dp < 6; dp++) {
                uint32_t vf[4];
                ldsm4t(vf, v_base + (kt2*16*QSTR + dp*16)*2);
                mma16816h(Oacc[2*dp],   pf, vf[0], vf[1]);
                mma16816h(Oacc[2*dp+1], pf, vf[2], vf[3]);
            }
        }
    }

    float inv_lo = 1.f / l_lo, inv_hi = 1.f / l_hi;
    int row_lo = b*NS + q0 + w*16 + (l >> 2);
    #pragma unroll
    for (int t = 0; t < 12; t++) {
        int col = h*HD + t*8 + (l & 3)*2;
        *reinterpret_cast<uint32_t*>(&g_o_b[(size_t)row_lo*CC + col]) =
            packbf(Oacc[t][0]*inv_lo, Oacc[t][1]*inv_lo);
        *reinterpret_cast<uint32_t*>(&g_o_b[(size_t)(row_lo+8)*CC + col]) =
            packbf(Oacc[t][2]*inv_hi, Oacc[t][3]*inv_hi);
    }
}

extern "C" void kernel_launch(void* const* d_in, const int* in_sizes, int n_in,
                              void* d_out, int out_size) {
    const float* xz       = (const float*)d_in[0];
    const float* xs       = (const float*)d_in[1];
    const float* state_t  = (const float*)d_in[2];
    const float* state_c  = (const float*)d_in[3];
    const float* Wdo_w    = (const float*)d_in[4];
    const float* Wdo_b    = (const float*)d_in[5];
    const float* Wdc_w    = (const float*)d_in[6];
    const float* Wdc_b    = (const float*)d_in[7];
    const float* Wup_w    = (const float*)d_in[8];
    const float* Wup_b    = (const float*)d_in[9];
    const float* te_td    = (const float*)d_in[10];
    const float* te_tf    = (const float*)d_in[11];
    const float* te_k     = (const float*)d_in[12];
    const float* te_v     = (const float*)d_in[13];
    const float* te_r     = (const float*)d_in[14];
    const float* te_o     = (const float*)d_in[15];
    const float* ce_td    = (const float*)d_in[16];
    const float* ce_tf    = (const float*)d_in[17];
    const float* ce_k     = (const float*)d_in[18];
    const float* ce_v     = (const float*)d_in[19];
    const float* ce_r     = (const float*)d_in[20];
    const float* ce_o     = (const float*)d_in[21];
    const float* qn_g     = (const float*)d_in[22];
    const float* qn_b     = (const float*)d_in[23];
    const float* fn_g     = (const float*)d_in[24];
    const float* fn_b     = (const float*)d_in[25];
    const float* attn_in_w  = (const float*)d_in[26];
    const float* attn_in_b  = (const float*)d_in[27];
    const float* attn_out_w = (const float*)d_in[28];
    const float* attn_out_b = (const float*)d_in[29];
    const float* router     = (const float*)d_in[30];
    float* out = (float*)d_out;

    cudaFuncSetAttribute(k_flash_bf, cudaFuncAttributeMaxDynamicSharedMemorySize, FL_SMEM);

    __nv_bfloat16 *gxq, *gf, *gq, *gk, *go, *gwq, *gwo;
    __half *gv;
    cudaGetSymbolAddress((void**)&gxq, g_xq_b);
    cudaGetSymbolAddress((void**)&gf,  g_f_b);
    cudaGetSymbolAddress((void**)&gq,  g_q_b);
    cudaGetSymbolAddress((void**)&gk,  g_k_b);
    cudaGetSymbolAddress((void**)&gv,  g_v_h);
    cudaGetSymbolAddress((void**)&go,  g_o_b);
    cudaGetSymbolAddress((void**)&gwq, g_wqkv_b);
    cudaGetSymbolAddress((void**)&gwo, g_wout_b);

    float *gxr, *gkvrv, *gy, *gtcv;
    cudaGetSymbolAddress((void**)&gxr,   g_xr);
    cudaGetSymbolAddress((void**)&gkvrv, g_kvrv);
    cudaGetSymbolAddress((void**)&gy,    g_y);
    cudaGetSymbolAddress((void**)&gtcv,  g_tcv);

    __nv_bfloat16 *wdh, *wdl, *kvh, *kvl, *wch, *wcl;
    cudaGetSymbolAddress((void**)&wdh, g_wd_h);
    cudaGetSymbolAddress((void**)&wdl, g_wd_l);
    cudaGetSymbolAddress((void**)&kvh, g_kvr_h);
    cudaGetSymbolAddress((void**)&kvl, g_kvr_l);
    cudaGetSymbolAddress((void**)&wch, g_wc_h);
    cudaGetSymbolAddress((void**)&wcl, g_wc_l);

    const int WD = RR*CC, WS = RR*RR;
    const int WSPLIT_N = 3*WD + 6*WS;

    k_zpart<<<BB*24, CC>>>(xz);
    k_zfin<<<BB, CC>>>();
    k_resp<<<NROW, 256>>>(xs);
    k_order<<<BB, NW>>>();
    k_prep<<<(VROW + 255)/256, 256>>>();
    k_wsplit<<<(WSPLIT_N + 255)/256, 256>>>(Wdo_w, Wdc_w, te_k, te_v, te_r,
                                            ce_k, ce_v, ce_r, Wup_w);
    k_wcomb<<<dim3(CC/16, 2), RR>>>(Wup_w, te_o, ce_o);
    k_wconv<<<(3*CC*CC/2 + 255)/256, 256>>>(attn_in_w, attn_out_w);

    // RWKV dense chain on tensor cores
    k_gemm3<<<dim3(VROW/128, RR/64), 256>>>(xs, CC, CC,
        wdh, wdl, wdh + WD, wdl + WD, Wdo_b, Wdc_b, gxr, RR, 0, nullptr);
    k_gemm3<<<dim3(VROW/128, 3*RR/64), 256>>>(gxr, RR, RR,
        kvh, kvl, kvh + 3*WS, kvl + 3*WS, nullptr, nullptr, gkvrv, 3*RR, 1, nullptr);
    k_point<<<VROW/8, RR>>>(state_t, state_c, te_td, te_tf, ce_td, ce_tf, out);
    // fused (y@wo^T)@Wup^T via Wcomb
    k_gemm3<<<dim3(VROW/128, CC/64), 256>>>(gy, RR, RR,
        wch, wcl, wch + CC*RR, wcl + CC*RR, Wup_b, Wup_b, gtcv, CC, 2, out);

    k_ln<<<NROW, 256>>>(xs, qn_g, qn_b, fn_g, fn_b);

    // attention GEMMs (128x64 tiles)
    dim3 gg(NROW/128, CC/64);
    k_gemm_bf<<<gg, 256>>>(gxq, gwq,            attn_in_b,        gq, nullptr, nullptr, nullptr, 0);
    k_gemm_bf<<<gg, 256>>>(gf,  gwq + CC*CC,    attn_in_b + CC,   gk, nullptr, nullptr, nullptr, 0);
    k_gemm_bf<<<gg, 256>>>(gf,  gwq + 2*CC*CC,  attn_in_b + 2*CC,
        reinterpret_cast<__nv_bfloat16*>(gv), nullptr, nullptr, nullptr, 3);

    k_flash_bf<<<BB*NH*18, 256, FL_SMEM>>>();

    k_gemm_bf<<<gg, 256>>>(go, gwo, attn_out_b, nullptr, out + OFF_XS, xs, router, 1);
}

// round 14
// speedup vs baseline: 1.1447x; 1.1447x over previous
#include <cuda_runtime.h>
#include <cuda_bf16.h>
#include <cuda_fp16.h>
#include <math.h>
#include <stdint.h>

#define BB 4
#define HS 48
#define CC 768
#define RR 192
#define NS 2304
#define NW 576
#define TOPK 3
#define NH 8
#define HD 96
#define NROW (BB*NS)
#define TROWS (BB*TOPK*4)
#define CROWS (BB*(NW-TOPK)*4)
#define VROW 9344

#define OFF_TP 0
#define SZ_TP  (BB*TOPK*4*CC)
#define OFF_XS (OFF_TP + SZ_TP)
#define SZ_XS  (NROW*CC)
#define OFF_ST (OFF_XS + SZ_XS)
#define SZ_ST  (3*TROWS*RR)
#define OFF_SC (OFF_ST + SZ_ST)

__device__ float g_zpart[BB*24*CC];
__device__ float g_zmean[BB*CC];
__device__ float g_zinv[BB];
__device__ float g_resp[BB*NS];
__device__ int   g_order[BB*NW];
__device__ int   g_msrc[VROW];
__device__ int   g_mtc[VROW];

__device__ float g_xr [(size_t)VROW*RR];
__device__ float g_kvrv[(size_t)VROW*3*RR];
__device__ float g_y  [(size_t)VROW*RR];
__device__ float g_o2 [(size_t)VROW*RR];
__device__ float g_tcv[(size_t)NROW*CC];

__device__ __nv_bfloat16 g_xq_b[(size_t)NROW*CC];
__device__ __nv_bfloat16 g_f_b [(size_t)NROW*CC];
__device__ __nv_bfloat16 g_q_b [(size_t)NROW*CC];
__device__ __nv_bfloat16 g_k_b [(size_t)NROW*CC];
__device__ __half        g_v_h [(size_t)NROW*CC];
__device__ __nv_bfloat16 g_o_b [(size_t)NROW*CC];
__device__ __nv_bfloat16 g_wqkv_b[3*CC*CC];
__device__ __nv_bfloat16 g_wout_b[CC*CC];

__device__ __nv_bfloat16 g_wd_h[2*RR*CC],    g_wd_l[2*RR*CC];
__device__ __nv_bfloat16 g_kvr_h[2*3*RR*RR], g_kvr_l[2*3*RR*RR];
__device__ __nv_bfloat16 g_wo_h[2*RR*RR],    g_wo_l[2*RR*RR];
__device__ __nv_bfloat16 g_wup_h[CC*RR],     g_wup_l[CC*RR];

// ------- helpers -------
__device__ __forceinline__ uint32_t smaddr(const void* p) {
    return (uint32_t)__cvta_generic_to_shared(p);
}
__device__ __forceinline__ void ldsm4(uint32_t* r, uint32_t a) {
    asm volatile("ldmatrix.sync.aligned.m8n8.x4.shared.b16 {%0,%1,%2,%3}, [%4];"
        : "=r"(r[0]), "=r"(r[1]), "=r"(r[2]), "=r"(r[3]) : "r"(a));
}
__device__ __forceinline__ void ldsm4t(uint32_t* r, uint32_t a) {
    asm volatile("ldmatrix.sync.aligned.m8n8.x4.trans.shared.b16 {%0,%1,%2,%3}, [%4];"
        : "=r"(r[0]), "=r"(r[1]), "=r"(r[2]), "=r"(r[3]) : "r"(a));
}
__device__ __forceinline__ void mma16816(float* d, const uint32_t* a, uint32_t b0, uint32_t b1) {
    asm volatile("mma.sync.aligned.m16n8k16.row.col.f32.bf16.bf16.f32 "
        "{%0,%1,%2,%3}, {%4,%5,%6,%7}, {%8,%9}, {%0,%1,%2,%3};"
        : "+f"(d[0]), "+f"(d[1]), "+f"(d[2]), "+f"(d[3])
        : "r"(a[0]), "r"(a[1]), "r"(a[2]), "r"(a[3]), "r"(b0), "r"(b1));
}
__device__ __forceinline__ void mma16816h(float* d, const uint32_t* a, uint32_t b0, uint32_t b1) {
    asm volatile("mma.sync.aligned.m16n8k16.row.col.f32.f16.f16.f32 "
        "{%0,%1,%2,%3}, {%4,%5,%6,%7}, {%8,%9}, {%0,%1,%2,%3};"
        : "+f"(d[0]), "+f"(d[1]), "+f"(d[2]), "+f"(d[3])
        : "r"(a[0]), "r"(a[1]), "r"(a[2]), "r"(a[3]), "r"(b0), "r"(b1));
}
__device__ __forceinline__ float ex2f(float x) {
    float y; asm("ex2.approx.f32 %0, %1;" : "=f"(y) : "f"(x)); return y;
}
__device__ __forceinline__ uint32_t h2ex2(uint32_t x) {
    uint32_t y; asm("ex2.approx.f16x2 %0, %1;" : "=r"(y) : "r"(x)); return y;
}
__device__ __forceinline__ uint32_t hadd2u(uint32_t a, uint32_t b) {
    uint32_t y; asm("add.rn.f16x2 %0, %1, %2;" : "=r"(y) : "r"(a), "r"(b)); return y;
}
__device__ __forceinline__ uint32_t packbf(float a, float b) {
    __nv_bfloat162 t = __floats2bfloat162_rn(a, b);
    return *reinterpret_cast<uint32_t*>(&t);
}
__device__ __forceinline__ uint32_t packh(float a, float b) {
    __half2 t = __floats2half2_rn(a, b);
    return *reinterpret_cast<uint32_t*>(&t);
}

// ---- K1a ----
__global__ __launch_bounds__(CC) void k_zpart(const float* __restrict__ xz) {
    int b = blockIdx.x / 24, chunk = blockIdx.x % 24;
    int c = threadIdx.x;
    const float* p = xz + ((size_t)b*NS + (size_t)chunk*96)*CC + c;
    float s = 0.f;
    #pragma unroll 4
    for (int n = 0; n < 96; n++) s += p[(size_t)n*CC];
    g_zpart[(b*24 + chunk)*CC + c] = s;
}

// ---- K1b ----
__global__ __launch_bounds__(CC) void k_zfin() {
    __shared__ float red[CC];
    int b = blockIdx.x, c = threadIdx.x;
    float s = 0.f;
    for (int j = 0; j < 24; j++) s += g_zpart[(b*24 + j)*CC + c];
    float zm = s * (1.f/NS);
    g_zmean[b*CC + c] = zm;
    red[c] = zm*zm;
    __syncthreads();
    for (int st = 512; st > 0; st >>= 1) {
        if (c < st && c + st < CC) red[c] += red[c+st];
        __syncthreads();
    }
    if (c == 0) g_zinv[b] = 1.f / fmaxf(sqrtf(red[0]), 1e-12f);
}

// ---- K2: resp ----
__global__ __launch_bounds__(256) void k_resp(const float* __restrict__ xs) {
    int row = blockIdx.x;
    int b = row / NS;
    const float* x = xs + (size_t)row*CC;
    const float* z = g_zmean + b*CC;
    float d = 0.f, xx = 0.f;
    for (int c = threadIdx.x; c < CC; c += 256) {
        float xv = x[c];
        d += xv * z[c];
        xx += xv * xv;
    }
    __shared__ float sd[8], sx2[8];
    int lane = threadIdx.x & 31, wid = threadIdx.x >> 5;
    for (int o = 16; o; o >>= 1) {
        d  += __shfl_down_sync(0xffffffffu, d, o);
        xx += __shfl_down_sync(0xffffffffu, xx, o);
    }
    if (lane == 0) { sd[wid] = d; sx2[wid] = xx; }
    __syncthreads();
    if (threadIdx.x == 0) {
        float D = 0.f, X = 0.f;
        for (int i = 0; i < 8; i++) { D += sd[i]; X += sx2[i]; }
        g_resp[row] = D * g_zinv[b] / fmaxf(sqrtf(X), 1e-12f);
    }
}

// ---- K3: window rank ----
__global__ __launch_bounds__(NW) void k_order() {
    __shared__ __align__(16) float wm[NW];
    int b = blockIdx.x, w = threadIdx.x;
    int wi = w / 24, wj = w % 24;
    int base = b*NS + (2*wi)*HS + 2*wj;
    float v = 0.25f*(g_resp[base] + g_resp[base+1] + g_resp[base+HS] + g_resp[base+HS+1]);
    wm[w] = v;
    __syncthreads();
    int rank = 0;
    const float4* wm4 = reinterpret_cast<const float4*>(wm);
    for (int j = 0; j < NW/4; j++) {
        float4 u = wm4[j];
        int j4 = 4*j;
        rank += (u.x > v || (u.x == v && j4   < w));
        rank += (u.y > v || (u.y == v && j4+1 < w));
        rank += (u.z > v || (u.z == v && j4+2 < w));
        rank += (u.w > v || (u.w == v && j4+3 < w));
    }
    g_order[b*NW + rank] = w;
}

// ---- prep ----
__global__ __launch_bounds__(256) void k_prep() {
    int vr = blockIdx.x*256 + threadIdx.x;
    if (vr >= VROW) return;
    int src = 0, tc = 0;
    bool valid = (vr < 48) || (vr >= 128 && vr < 9296);
    if (valid) {
        int b, p, t;
        if (vr < 48) { b = vr/12; int m = vr%12; p = m>>2; t = m&3; tc = b*NS + m; }
        else { int rp = vr-128; b = rp/2292; int mm = rp%2292; p = TOPK + (mm>>2); t = mm&3; tc = b*NS + 12 + mm; }
        int w = g_order[b*NW + p];
        int wi = w / 24, wj = w % 24;
        src = b*NS + (2*wi + (t>>1))*HS + 2*wj + (t&1);
    }
    g_msrc[vr] = src;
    g_mtc[vr]  = tc;
}

// ---- weight split ----
__global__ __launch_bounds__(256) void k_wsplit(
    const float* __restrict__ Wdo_w, const float* __restrict__ Wdc_w,
    const float* __restrict__ te_k, const float* __restrict__ te_v, const float* __restrict__ te_r,
    const float* __restrict__ ce_k, const float* __restrict__ ce_v, const float* __restrict__ ce_r,
    const float* __restrict__ te_o, const float* __restrict__ ce_o,
    const float* __restrict__ Wup_w)
{
    int i = blockIdx.x*256 + threadIdx.x;
    const int WD = RR*CC;
    const int WS = RR*RR;
    float v; __nv_bfloat16* hp; __nv_bfloat16* lp; int o;
    if      (i < WD)            { v = Wdo_w[i];        hp = g_wd_h;  lp = g_wd_l;  o = i; }
    else if (i < 2*WD)          { v = Wdc_w[i-WD];     hp = g_wd_h;  lp = g_wd_l;  o = i; }
    else if (i < 2*WD + WS)     { v = te_k[i-2*WD];          hp = g_kvr_h; lp = g_kvr_l; o = i-2*WD; }
    else if (i < 2*WD + 2*WS)   { v = te_v[i-2*WD-WS];       hp = g_kvr_h; lp = g_kvr_l; o = i-2*WD; }
    else if (i < 2*WD + 3*WS)   { v = te_r[i-2*WD-2*WS];     hp = g_kvr_h; lp = g_kvr_l; o = i-2*WD; }
    else if (i < 2*WD + 4*WS)   { v = ce_k[i-2*WD-3*WS];     hp = g_kvr_h; lp = g_kvr_l; o = i-2*WD; }
    else if (i < 2*WD + 5*WS)   { v = ce_v[i-2*WD-4*WS];     hp = g_kvr_h; lp = g_kvr_l; o = i-2*WD; }
    else if (i < 2*WD + 6*WS)   { v = ce_r[i-2*WD-5*WS];     hp = g_kvr_h; lp = g_kvr_l; o = i-2*WD; }
    else if (i < 2*WD + 7*WS)   { v = te_o[i-2*WD-6*WS];     hp = g_wo_h;  lp = g_wo_l;  o = i-2*WD-6*WS; }
    else if (i < 2*WD + 8*WS)   { v = ce_o[i-2*WD-7*WS];     hp = g_wo_h;  lp = g_wo_l;  o = i-2*WD-6*WS; }
    else if (i < 3*WD + 8*WS)   { v = Wup_w[i-2*WD-8*WS];    hp = g_wup_h; lp = g_wup_l; o = i-2*WD-8*WS; }
    else return;
    __nv_bfloat16 h = __float2bfloat16_rn(v);
    hp[o] = h;
    lp[o] = __float2bfloat16_rn(v - __bfloat162float(h));
}

// ---- split-precision tensor GEMM (RWKV chain) ----
#define GSTR 40
__global__ __launch_bounds__(256) void k_gemm3(
    const float* __restrict__ A, int lda, int K,
    const __nv_bfloat16* __restrict__ Bh0, const __nv_bfloat16* __restrict__ Bl0,
    const __nv_bfloat16* __restrict__ Bh1, const __nv_bfloat16* __restrict__ Bl1,
    const float* __restrict__ bias0, const float* __restrict__ bias1,
    float* __restrict__ C, int ldc, int mode, float* __restrict__ out)
{
    __shared__ __nv_bfloat16 Ah[128*GSTR], Al[128*GSTR];
    __shared__ __nv_bfloat16 Bhs[64*GSTR], Bls[64*GSTR];
    int m0 = blockIdx.x * 128, n0 = blockIdx.y * 64;
    bool e0 = (blockIdx.x == 0);
    const __nv_bfloat16* Bhp = e0 ? Bh0 : Bh1;
    const __nv_bfloat16* Blp = e0 ? Bl0 : Bl1;
    const float* bias = e0 ? bias0 : bias1;
    int tid = threadIdx.x, l = tid & 31, w = tid >> 5;
    int mw = (w >> 1) * 32, nw = (w & 1) * 32;
    int ar = tid >> 1, ac = (tid & 1) * 16;
    int br = tid >> 2, bc = (tid & 3) * 8;

    const float* Arow = A + (size_t)((mode == 0) ? g_msrc[m0+ar] : (m0+ar))*lda;

    float acc[2][4][4];
    #pragma unroll
    for (int mi = 0; mi < 2; mi++)
        #pragma unroll
        for (int nj = 0; nj < 4; nj++)
            #pragma unroll
            for (int q = 0; q < 4; q++) acc[mi][nj][q] = 0.f;

    float4 fa[4]; uint4 rbh, rbl;
    #pragma unroll
    for (int j = 0; j < 4; j++) fa[j] = *reinterpret_cast<const float4*>(Arow + ac + 4*j);
    rbh = *reinterpret_cast<const uint4*>(Bhp + (size_t)(n0+br)*K + bc);
    rbl = *reinterpret_cast<const uint4*>(Blp + (size_t)(n0+br)*K + bc);

    int g = l >> 3, lg = l & 7;
    uint32_t aoff = (uint32_t)(((mw + (l & 15))*GSTR + ((l >> 4) << 3)) * 2);
    uint32_t ah_base = smaddr(Ah) + aoff;
    uint32_t al_base = smaddr(Al) + aoff;
    uint32_t boff = (uint32_t)(((nw + ((g & 2) ? 8 : 0) + lg)*GSTR + ((g & 1) ? 8 : 0)) * 2);
    uint32_t bh_base = smaddr(Bhs) + boff;
    uint32_t bl_base = smaddr(Bls) + boff;

    for (int kc = 0; kc < K; kc += 32) {
        #pragma unroll
        for (int j = 0; j < 4; j++) {
            float vals[4] = {fa[j].x, fa[j].y, fa[j].z, fa[j].w};
            #pragma unroll
            for (int e = 0; e < 4; e += 2) {
                float v0 = vals[e], v1 = vals[e+1];
                uint32_t hp = packbf(v0, v1);
                __nv_bfloat162 hh = *reinterpret_cast<__nv_bfloat162*>(&hp);
                float l0 = v0 - __bfloat162float(hh.x);
                float l1 = v1 - __bfloat162float(hh.y);
                int col = ac + 4*j + e;
                *reinterpret_cast<uint32_t*>(&Ah[ar*GSTR + col]) = hp;
                *reinterpret_cast<uint32_t*>(&Al[ar*GSTR + col]) = packbf(l0, l1);
            }
        }
        *reinterpret_cast<uint4*>(&Bhs[br*GSTR + bc]) = rbh;
        *reinterpret_cast<uint4*>(&Bls[br*GSTR + bc]) = rbl;
        __syncthreads();
        if (kc + 32 < K) {
            #pragma unroll
            for (int j = 0; j < 4; j++)
                fa[j] = *reinterpret_cast<const float4*>(Arow + kc + 32 + ac + 4*j);
            rbh = *reinterpret_cast<const uint4*>(Bhp + (size_t)(n0+br)*K + kc + 32 + bc);
            rbl = *reinterpret_cast<const uint4*>(Blp + (size_t)(n0+br)*K + kc + 32 + bc);
        }
        #pragma unroll
        for (int kk = 0; kk < 2; kk++) {
            uint32_t ah[2][4], alr[2][4];
            ldsm4(ah[0],  ah_base + (kk*16)*2);
            ldsm4(ah[1],  ah_base + (16*GSTR + kk*16)*2);
            ldsm4(alr[0], al_base + (kk*16)*2);
            ldsm4(alr[1], al_base + (16*GSTR + kk*16)*2);
            #pragma unroll
            for (int np = 0; np < 2; np++) {
                uint32_t bh[4], bl2[4];
                ldsm4(bh,  bh_base + (np*16*GSTR + kk*16)*2);
                ldsm4(bl2, bl_base + (np*16*GSTR + kk*16)*2);
                #pragma unroll
                for (int mi = 0; mi < 2; mi++) {
                    mma16816(acc[mi][2*np],   ah[mi],  bh[0],  bh[1]);
                    mma16816(acc[mi][2*np],   ah[mi],  bl2[0], bl2[1]);
                    mma16816(acc[mi][2*np],   alr[mi], bh[0],  bh[1]);
                    mma16816(acc[mi][2*np+1], ah[mi],  bh[2],  bh[3]);
                    mma16816(acc[mi][2*np+1], ah[mi],  bl2[2], bl2[3]);
                    mma16816(acc[mi][2*np+1], alr[mi], bh[2],  bh[3]);
                }
            }
        }
        __syncthreads();
    }

    #pragma unroll
    for (int mi = 0; mi < 2; mi++) {
        int row_lo = m0 + mw + mi*16 + (l >> 2);
        #pragma unroll
        for (int nj = 0; nj < 4; nj++) {
            int col = n0 + nw + nj*8 + (l & 3)*2;
            float b0 = bias ? bias[col]   : 0.f;
            float b1 = bias ? bias[col+1] : 0.f;
            float c0 = acc[mi][nj][0] + b0, c1 = acc[mi][nj][1] + b1;
            float c2 = acc[mi][nj][2] + b0, c3 = acc[mi][nj][3] + b1;
            if (mode < 2) {
                size_t plo = (size_t)row_lo*ldc + col;
                size_t phi = (size_t)(row_lo+8)*ldc + col;
                C[plo] = c0; C[plo+1] = c1;
                C[phi] = c2; C[phi+1] = c3;
            } else {
                int vr0 = row_lo, vr1 = row_lo + 8;
                if (vr0 < 48 || (vr0 >= 128 && vr0 < 9296)) {
                    size_t p = (size_t)g_mtc[vr0]*CC + col;
                    C[p] = c0; C[p+1] = c1;
                    if (vr0 < 48) { out[OFF_TP + (size_t)vr0*CC + col] = c0; out[OFF_TP + (size_t)vr0*CC + col + 1] = c1; }
                }
                if (vr1 < 48 || (vr1 >= 128 && vr1 < 9296)) {
                    size_t p = (size_t)g_mtc[vr1]*CC + col;
                    C[p] = c2; C[p+1] = c3;
                    if (vr1 < 48) { out[OFF_TP + (size_t)vr1*CC + col] = c2; out[OFF_TP + (size_t)vr1*CC + col + 1] = c3; }
                }
            }
        }
    }
}

// ---- pointwise RWKV state update ----
__global__ __launch_bounds__(RR) void k_point(
    const float* __restrict__ state_t, const float* __restrict__ state_c,
    const float* __restrict__ te_td, const float* __restrict__ te_tf,
    const float* __restrict__ ce_td, const float* __restrict__ ce_tf,
    float* __restrict__ out)
{
    int n = threadIdx.x;
    int vr0 = blockIdx.x * 8;
    #pragma unroll
    for (int i = 0; i < 8; i++) {
        int vr = vr0 + i;
        bool top = (vr < 48);
        if (!top && (vr < 128 || vr >= 9296)) continue;
        const float* st = top ? state_t : state_c;
        int srow = top ? vr : vr - 128;
        size_t nplane = top ? (size_t)TROWS*RR : (size_t)CROWS*RR;
        float* ost = out + (top ? OFF_ST : OFF_SC);

        float kk = g_kvrv[(size_t)vr*(3*RR) + n];
        float vv = g_kvrv[(size_t)vr*(3*RR) + RR + n];
        float rr = g_kvrv[(size_t)vr*(3*RR) + 2*RR + n];
        float td = (top ? te_td : ce_td)[n];
        float tf = (top ? te_tf : ce_tf)[n];
        float wexp = expf(td);

        float rv = 1.f / (1.f + expf(-rr));
        size_t base = (size_t)srow*RR + n;
        float aa = st[base], bb = st[nplane + base], pp = st[2*nplane + base];
        float ww = tf + kk;
        float pm = fmaxf(pp, ww);
        float e1 = expf(pp - pm), e2 = expf(ww - pm);
        float wkv = (e1*aa + e2*vv) / (e1*bb + e2);
        float ww2 = pp - wexp;
        float p2 = fmaxf(ww2, kk);
        float f1 = expf(ww2 - p2), f2 = expf(kk - p2);
        ost[base]            = f1*aa + f2*vv;
        ost[nplane + base]   = f1*bb + f2;
        ost[2*nplane + base] = p2;
        g_y[(size_t)vr*RR + n] = rv * wkv;
    }
}

// ---- K5: LN -> bf16 ----
__global__ __launch_bounds__(256) void k_ln(const float* __restrict__ xs,
    const float* __restrict__ qn_g, const float* __restrict__ qn_b,
    const float* __restrict__ fn_g, const float* __restrict__ fn_b)
{
    __shared__ float row[CC];
    __shared__ float warpred[8];
    __shared__ float stat[2];
    int idx = blockIdx.x;
    bool isf = (idx >= NROW);
    int r = isf ? idx - NROW : idx;
    const float* src = isf ? g_tcv + (size_t)r*CC : xs + (size_t)r*CC;
    __nv_bfloat16* dst = isf ? g_f_b + (size_t)r*CC : g_xq_b + (size_t)r*CC;
    const float* gg = isf ? fn_g : qn_g;
    const float* bb = isf ? fn_b : qn_b;
    int tid = threadIdx.x, lane = tid & 31, wid = tid >> 5;

    float s = 0.f;
    for (int c = tid; c < CC; c += 256) { float v = src[c]; row[c] = v; s += v; }
    for (int o = 16; o; o >>= 1) s += __shfl_down_sync(0xffffffffu, s, o);
    if (lane == 0) warpred[wid] = s;
    __syncthreads();
    if (tid == 0) { float t = 0.f; for (int i = 0; i < 8; i++) t += warpred[i]; stat[0] = t * (1.f/CC); }
    __syncthreads();
    float m = stat[0], vs = 0.f;
    for (int c = tid; c < CC; c += 256) { float d = row[c] - m; vs += d*d; }
    for (int o = 16; o; o >>= 1) vs += __shfl_down_sync(0xffffffffu, vs, o);
    if (lane == 0) warpred[wid] = vs;
    __syncthreads();
    if (tid == 0) { float t = 0.f; for (int i = 0; i < 8; i++) t += warpred[i]; stat[1] = rsqrtf(t*(1.f/CC) + 1e-6f); }
    __syncthreads();
    float inv = stat[1];
    for (int c = tid; c < CC; c += 256)
        dst[c] = __float2bfloat16_rn((row[c] - m) * inv * gg[c] + bb[c]);
}

// ---- attention weight convert ----
__global__ __launch_bounds__(256) void k_wconv(const float* __restrict__ win,
                                              const float* __restrict__ wout) {
    int i = blockIdx.x*256 + threadIdx.x;
    int p = i*2;
    if (p < 3*CC*CC) {
        *reinterpret_cast<uint32_t*>(&g_wqkv_b[p]) = packbf(win[p], win[p+1]);
    }
    if (p < CC*CC) {
        *reinterpret_cast<uint32_t*>(&g_wout_b[p]) = packbf(wout[p], wout[p+1]);
    }
}

// ---- K6: bf16 tensor-core GEMM 128x64 ----
#define ASTR 40
__global__ __launch_bounds__(256) void k_gemm_bf(
    const __nv_bfloat16* __restrict__ A, const __nv_bfloat16* __restrict__ W,
    const float* __restrict__ bias, __nv_bfloat16* __restrict__ dstb,
    float* __restrict__ dstf, const float* __restrict__ xs,
    const float* __restrict__ router, int mode)
{
    __shared__ __nv_bfloat16 As[128*ASTR];
    __shared__ __nv_bfloat16 Bs[64*ASTR];
    int m0 = blockIdx.x * 128, n0 = blockIdx.y * 64;
    int tid = threadIdx.x;
    int l = tid & 31, w = tid >> 5;
    int mw = (w >> 1) * 32, nw = (w & 1) * 32;
    int ldr = tid >> 2, ldc = (tid & 3) * 8;

    float acc[2][4][4];
    #pragma unroll
    for (int mi = 0; mi < 2; mi++)
        #pragma unroll
        for (int nj = 0; nj < 4; nj++)
            #pragma unroll
            for (int q = 0; q < 4; q++) acc[mi][nj][q] = 0.f;

    uint4 ra0, ra1, rb;
    ra0 = *reinterpret_cast<const uint4*>(A + (size_t)(m0+ldr)*CC + ldc);
    ra1 = *reinterpret_cast<const uint4*>(A + (size_t)(m0+64+ldr)*CC + ldc);
    rb  = *reinterpret_cast<const uint4*>(W + (size_t)(n0+ldr)*CC + ldc);

    int g = l >> 3, lg = l & 7;
    uint32_t a_base = smaddr(As) + (uint32_t)(((mw + (l & 15))*ASTR + ((l >> 4) << 3)) * 2);
    uint32_t b_base = smaddr(Bs) + (uint32_t)(((nw + ((g & 2) ? 8 : 0) + lg)*ASTR + ((g & 1) ? 8 : 0)) * 2);

    for (int kc = 0; kc < CC; kc += 32) {
        *reinterpret_cast<uint4*>(&As[ldr*ASTR + ldc])      = ra0;
        *reinterpret_cast<uint4*>(&As[(64+ldr)*ASTR + ldc]) = ra1;
        *reinterpret_cast<uint4*>(&Bs[ldr*ASTR + ldc])      = rb;
        __syncthreads();
        if (kc + 32 < CC) {
            ra0 = *reinterpret_cast<const uint4*>(A + (size_t)(m0+ldr)*CC + kc + 32 + ldc);
            ra1 = *reinterpret_cast<const uint4*>(A + (size_t)(m0+64+ldr)*CC + kc + 32 + ldc);
            rb  = *reinterpret_cast<const uint4*>(W + (size_t)(n0+ldr)*CC + kc + 32 + ldc);
        }
        #pragma unroll
        for (int kk = 0; kk < 2; kk++) {
            uint32_t af[2][4];
            ldsm4(af[0], a_base + (kk*16)*2);
            ldsm4(af[1], a_base + (16*ASTR + kk*16)*2);
            #pragma unroll
            for (int np = 0; np < 2; np++) {
                uint32_t bf[4];
                ldsm4(bf, b_base + (np*16*ASTR + kk*16)*2);
                #pragma unroll
                for (int mi = 0; mi < 2; mi++) {
                    mma16816(acc[mi][2*np],   af[mi], bf[0], bf[1]);
                    mma16816(acc[mi][2*np+1], af[mi], bf[2], bf[3]);
                }
            }
        }
        __syncthreads();
    }

    #pragma unroll
    for (int mi = 0; mi < 2; mi++) {
        int row_lo = m0 + mw + mi*16 + (l >> 2);
        #pragma unroll
        for (int nj = 0; nj < 4; nj++) {
            int col = n0 + nw + nj*8 + (l & 3)*2;
            float b0 = bias[col], b1 = bias[col+1];
            float c0 = acc[mi][nj][0] + b0, c1 = acc[mi][nj][1] + b1;
            float c2 = acc[mi][nj][2] + b0, c3 = acc[mi][nj][3] + b1;
            size_t plo = (size_t)row_lo*CC + col;
            size_t phi = (size_t)(row_lo+8)*CC + col;
            if (mode == 0) {
                *reinterpret_cast<uint32_t*>(&dstb[plo]) = packbf(c0, c1);
                *reinterpret_cast<uint32_t*>(&dstb[phi]) = packbf(c2, c3);
            } else if (mode == 3) {
                __half* dh = reinterpret_cast<__half*>(dstb);
                *reinterpret_cast<uint32_t*>(&dh[plo]) = packh(c0, c1);
                *reinterpret_cast<uint32_t*>(&dh[phi]) = packh(c2, c3);
            } else {
                float r0 = router[col], r1 = router[col+1];
                dstf[plo]   = xs[plo]   + r0*c0;
                dstf[plo+1] = xs[plo+1] + r1*c1;
                dstf[phi]   = xs[phi]   + r0*c2;
                dstf[phi+1] = xs[phi+1] + r1*c3;
            }
        }
    }
}

// ---- K7: flash attention (register-staged KV prefetch) ----
#define QSTR 104
#define FL_Q 0
#define FL_K (128*QSTR)
#define FL_V (FL_K + 64*QSTR)
#define FL_SMEM ((FL_V + 64*QSTR)*2)

__global__ __launch_bounds__(256) void k_flash_bf() {
    extern __shared__ __align__(16) __nv_bfloat16 fsm[];
    __nv_bfloat16* Qs = fsm + FL_Q;
    __nv_bfloat16* Ks = fsm + FL_K;
    __nv_bfloat16* Vs = fsm + FL_V;   // holds __half data

    int blk = blockIdx.x;
    int qt = blk % 18;
    int h  = (blk / 18) % NH;
    int b  = blk / (18*NH);
    int q0 = qt * 128;
    int tid = threadIdx.x;
    int l = tid & 31, w = tid >> 5;
    int g = l >> 3, lg = l & 7;
    const float sc2 = 0.14725602686637387f;  // log2(e)/sqrt(96)

    for (int i = tid; i < 128*12; i += 256) {
        int r = i / 12, j = i % 12;
        *reinterpret_cast<uint4*>(&Qs[r*QSTR + j*8]) =
            *reinterpret_cast<const uint4*>(&g_q_b[(size_t)(b*NS + q0 + r)*CC + h*HD + j*8]);
    }

    float Oacc[12][4];
    float m_lo = -1e30f, m_hi = -1e30f, l_lo = 0.f, l_hi = 0.f;
    #pragma unroll
    for (int t = 0; t < 12; t++)
        #pragma unroll
        for (int q = 0; q < 4; q++) Oacc[t][q] = 0.f;

    uint32_t q_base = smaddr(Qs) + (uint32_t)(((w*16 + (l & 15))*QSTR + ((l >> 4) << 3)) * 2);
    uint32_t k_base = smaddr(Ks) + (uint32_t)((((g & 2) ? 8 : 0) + lg)*QSTR + ((g & 1) ? 8 : 0)) * 2;
    uint32_t v_base = smaddr(Vs) + (uint32_t)((((g & 1) ? 8 : 0) + lg)*QSTR + ((g & 2) ? 8 : 0)) * 2;

    uint4 kr[3], vr[3];
    #pragma unroll
    for (int c = 0; c < 3; c++) {
        int i = tid + c*256;
        int r = i / 12, j = i % 12;
        kr[c] = *reinterpret_cast<const uint4*>(&g_k_b[(size_t)(b*NS + r)*CC + h*HD + j*8]);
        vr[c] = *reinterpret_cast<const uint4*>(&g_v_h[(size_t)(b*NS + r)*CC + h*HD + j*8]);
    }

    for (int kt = 0; kt < 36; kt++) {
        __syncthreads();
        #pragma unroll
        for (int c = 0; c < 3; c++) {
            int i = tid + c*256;
            int r = i / 12, j = i % 12;
            *reinterpret_cast<uint4*>(&Ks[r*QSTR + j*8]) = kr[c];
            *reinterpret_cast<uint4*>(&Vs[r*QSTR + j*8]) = vr[c];
        }
        __syncthreads();
        if (kt + 1 < 36) {
            int k0n = (kt + 1) * 64;
            #pragma unroll
            for (int c = 0; c < 3; c++) {
                int i = tid + c*256;
                int r = i / 12, j = i % 12;
                kr[c] = *reinterpret_cast<const uint4*>(&g_k_b[(size_t)(b*NS + k0n + r)*CC + h*HD + j*8]);
                vr[c] = *reinterpret_cast<const uint4*>(&g_v_h[(size_t)(b*NS + k0n + r)*CC + h*HD + j*8]);
            }
        }

        // S = Q @ K^T (bf16)
        float sacc[8][4];
        #pragma unroll
        for (int j = 0; j < 8; j++)
            #pragma unroll
            for (int q = 0; q < 4; q++) sacc[j][q] = 0.f;
        #pragma unroll
        for (int d = 0; d < 6; d++) {
            uint32_t af[4];
            ldsm4(af, q_base + (d*16)*2);
            #pragma unroll
            for (int np = 0; np < 4; np++) {
                uint32_t bf[4];
                ldsm4(bf, k_base + (np*16*QSTR + d*16)*2);
                mma16816(sacc[2*np],   af, bf[0], bf[1]);
                mma16816(sacc[2*np+1], af, bf[2], bf[3]);
            }
        }

        // online softmax: max in fp32, exp via ex2.approx.f16x2
        float mx_lo = -1e30f, mx_hi = -1e30f;
        #pragma unroll
        for (int j = 0; j < 8; j++) {
            mx_lo = fmaxf(mx_lo, fmaxf(sacc[j][0], sacc[j][1]));
            mx_hi = fmaxf(mx_hi, fmaxf(sacc[j][2], sacc[j][3]));
        }
        mx_lo *= sc2; mx_hi *= sc2;
        mx_lo = fmaxf(mx_lo, __shfl_xor_sync(0xffffffffu, mx_lo, 1));
        mx_lo = fmaxf(mx_lo, __shfl_xor_sync(0xffffffffu, mx_lo, 2));
        mx_hi = fmaxf(mx_hi, __shfl_xor_sync(0xffffffffu, mx_hi, 1));
        mx_hi = fmaxf(mx_hi, __shfl_xor_sync(0xffffffffu, mx_hi, 2));
        float mn_lo = fmaxf(m_lo, mx_lo), mn_hi = fmaxf(m_hi, mx_hi);
        float al_lo = ex2f(m_lo - mn_lo), al_hi = ex2f(m_hi - mn_hi);

        uint32_t ph[8][2];
        #pragma unroll
        for (int j = 0; j < 8; j++) {
            float x0 = fmaf(sacc[j][0], sc2, -mn_lo);
            float x1 = fmaf(sacc[j][1], sc2, -mn_lo);
            float x2 = fmaf(sacc[j][2], sc2, -mn_hi);
            float x3 = fmaf(sacc[j][3], sc2, -mn_hi);
            ph[j][0] = h2ex2(packh(x0, x1));
            ph[j][1] = h2ex2(packh(x2, x3));
        }
        uint32_t slo = hadd2u(hadd2u(hadd2u(ph[0][0], ph[1][0]), hadd2u(ph[2][0], ph[3][0])),
                              hadd2u(hadd2u(ph[4][0], ph[5][0]), hadd2u(ph[6][0], ph[7][0])));
        uint32_t shi = hadd2u(hadd2u(hadd2u(ph[0][1], ph[1][1]), hadd2u(ph[2][1], ph[3][1])),
                              hadd2u(hadd2u(ph[4][1], ph[5][1]), hadd2u(ph[6][1], ph[7][1])));
        __half2 hlo = *reinterpret_cast<__half2*>(&slo);
        __half2 hhi = *reinterpret_cast<__half2*>(&shi);
        float rs_lo = __low2float(hlo) + __high2float(hlo);
        float rs_hi = __low2float(hhi) + __high2float(hhi);
        rs_lo += __shfl_xor_sync(0xffffffffu, rs_lo, 1);
        rs_lo += __shfl_xor_sync(0xffffffffu, rs_lo, 2);
        rs_hi += __shfl_xor_sync(0xffffffffu, rs_hi, 1);
        rs_hi += __shfl_xor_sync(0xffffffffu, rs_hi, 2);
        l_lo = l_lo*al_lo + rs_lo;
        l_hi = l_hi*al_hi + rs_hi;
        m_lo = mn_lo; m_hi = mn_hi;
        #pragma unroll
        for (int t = 0; t < 12; t++) {
            Oacc[t][0] *= al_lo; Oacc[t][1] *= al_lo;
            Oacc[t][2] *= al_hi; Oacc[t][3] *= al_hi;
        }

        // P @ V in fp16
        #pragma unroll
        for (int kt2 = 0; kt2 < 4; kt2++) {
            uint32_t pf[4];
            pf[0] = ph[2*kt2][0];
            pf[1] = ph[2*kt2][1];
            pf[2] = ph[2*kt2+1][0];
            pf[3] = ph[2*kt2+1][1];
            #pragma unroll
            for (int dp = 0; dp < 6; dp++) {
                uint32_t vf[4];
                ldsm4t(vf, v_base + (kt2*16*QSTR + dp*16)*2);
                mma16816h(Oacc[2*dp],   pf, vf[0], vf[1]);
                mma16816h(Oacc[2*dp+1], pf, vf[2], vf[3]);
            }
        }
    }

    float inv_lo = 1.f / l_lo, inv_hi = 1.f / l_hi;
    int row_lo = b*NS + q0 + w*16 + (l >> 2);
    #pragma unroll
    for (int t = 0; t < 12; t++) {
        int col = h*HD + t*8 + (l & 3)*2;
        *reinterpret_cast<uint32_t*>(&g_o_b[(size_t)row_lo*CC + col]) =
            packbf(Oacc[t][0]*inv_lo, Oacc[t][1]*inv_lo);
        *reinterpret_cast<uint32_t*>(&g_o_b[(size_t)(row_lo+8)*CC + col]) =
            packbf(Oacc[t][2]*inv_hi, Oacc[t][3]*inv_hi);
    }
}

extern "C" void kernel_launch(void* const* d_in, const int* in_sizes, int n_in,
                              void* d_out, int out_size) {
    const float* xz       = (const float*)d_in[0];
    const float* xs       = (const float*)d_in[1];
    const float* state_t  = (const float*)d_in[2];
    const float* state_c  = (const float*)d_in[3];
    const float* Wdo_w    = (const float*)d_in[4];
    const float* Wdo_b    = (const float*)d_in[5];
    const float* Wdc_w    = (const float*)d_in[6];
    const float* Wdc_b    = (const float*)d_in[7];
    const float* Wup_w    = (const float*)d_in[8];
    const float* Wup_b    = (const float*)d_in[9];
    const float* te_td    = (const float*)d_in[10];
    const float* te_tf    = (const float*)d_in[11];
    const float* te_k     = (const float*)d_in[12];
    const float* te_v     = (const float*)d_in[13];
    const float* te_r     = (const float*)d_in[14];
    const float* te_o     = (const float*)d_in[15];
    const float* ce_td    = (const float*)d_in[16];
    const float* ce_tf    = (const float*)d_in[17];
    const float* ce_k     = (const float*)d_in[18];
    const float* ce_v     = (const float*)d_in[19];
    const float* ce_r     = (const float*)d_in[20];
    const float* ce_o     = (const float*)d_in[21];
    const float* qn_g     = (const float*)d_in[22];
    const float* qn_b     = (const float*)d_in[23];
    const float* fn_g     = (const float*)d_in[24];
    const float* fn_b     = (const float*)d_in[25];
    const float* attn_in_w  = (const float*)d_in[26];
    const float* attn_in_b  = (const float*)d_in[27];
    const float* attn_out_w = (const float*)d_in[28];
    const float* attn_out_b = (const float*)d_in[29];
    const float* router     = (const float*)d_in[30];
    float* out = (float*)d_out;

    cudaFuncSetAttribute(k_flash_bf, cudaFuncAttributeMaxDynamicSharedMemorySize, FL_SMEM);

    __nv_bfloat16 *gxq, *gf, *gq, *gk, *go, *gwq, *gwo;
    __half *gv;
    cudaGetSymbolAddress((void**)&gxq, g_xq_b);
    cudaGetSymbolAddress((void**)&gf,  g_f_b);
    cudaGetSymbolAddress((void**)&gq,  g_q_b);
    cudaGetSymbolAddress((void**)&gk,  g_k_b);
    cudaGetSymbolAddress((void**)&gv,  g_v_h);
    cudaGetSymbolAddress((void**)&go,  g_o_b);
    cudaGetSymbolAddress((void**)&gwq, g_wqkv_b);
    cudaGetSymbolAddress((void**)&gwo, g_wout_b);

    float *gxr, *gkvrv, *gy, *go2, *gtcv;
    cudaGetSymbolAddress((void**)&gxr,   g_xr);
    cudaGetSymbolAddress((void**)&gkvrv, g_kvrv);
    cudaGetSymbolAddress((void**)&gy,    g_y);
    cudaGetSymbolAddress((void**)&go2,   g_o2);
    cudaGetSymbolAddress((void**)&gtcv,  g_tcv);

    __nv_bfloat16 *wdh, *wdl, *kvh, *kvl, *woh, *wol, *wuh, *wul;
    cudaGetSymbolAddress((void**)&wdh, g_wd_h);
    cudaGetSymbolAddress((void**)&wdl, g_wd_l);
    cudaGetSymbolAddress((void**)&kvh, g_kvr_h);
    cudaGetSymbolAddress((void**)&kvl, g_kvr_l);
    cudaGetSymbolAddress((void**)&woh, g_wo_h);
    cudaGetSymbolAddress((void**)&wol, g_wo_l);
    cudaGetSymbolAddress((void**)&wuh, g_wup_h);
    cudaGetSymbolAddress((void**)&wul, g_wup_l);

    const int WD = RR*CC, WS = RR*RR;
    const int WSPLIT_N = 3*WD + 8*WS;

    k_zpart<<<BB*24, CC>>>(xz);
    k_zfin<<<BB, CC>>>();
    k_resp<<<NROW, 256>>>(xs);
    k_order<<<BB, NW>>>();
    k_prep<<<(VROW + 255)/256, 256>>>();
    k_wsplit<<<(WSPLIT_N + 255)/256, 256>>>(Wdo_w, Wdc_w, te_k, te_v, te_r,
                                            ce_k, ce_v, ce_r, te_o, ce_o, Wup_w);
    k_wconv<<<(3*CC*CC/2 + 255)/256, 256>>>(attn_in_w, attn_out_w);

    // RWKV dense chain on tensor cores
    k_gemm3<<<dim3(VROW/128, RR/64), 256>>>(xs, CC, CC,
        wdh, wdl, wdh + WD, wdl + WD, Wdo_b, Wdc_b, gxr, RR, 0, nullptr);
    k_gemm3<<<dim3(VROW/128, 3*RR/64), 256>>>(gxr, RR, RR,
        kvh, kvl, kvh + 3*WS, kvl + 3*WS, nullptr, nullptr, gkvrv, 3*RR, 1, nullptr);
    k_point<<<VROW/8, RR>>>(state_t, state_c, te_td, te_tf, ce_td, ce_tf, out);
    k_gemm3<<<dim3(VROW/128, RR/64), 256>>>(gy, RR, RR,
        woh, wol, woh + WS, wol + WS, nullptr, nullptr, go2, RR, 1, nullptr);
    k_gemm3<<<dim3(VROW/128, CC/64), 256>>>(go2, RR, RR,
        wuh, wul, wuh, wul, Wup_b, Wup_b, gtcv, CC, 2, out);

    k_ln<<<2*NROW, 256>>>(xs, qn_g, qn_b, fn_g, fn_b);

    // attention GEMMs (128x64 tiles)
    dim3 gg(NROW/128, CC/64);
    k_gemm_bf<<<gg, 256>>>(gxq, gwq,            attn_in_b,        gq, nullptr, nullptr, nullptr, 0);
    k_gemm_bf<<<gg, 256>>>(gf,  gwq + CC*CC,    attn_in_b + CC,   gk, nullptr, nullptr, nullptr, 0);
    k_gemm_bf<<<gg, 256>>>(gf,  gwq + 2*CC*CC,  attn_in_b + 2*CC,
        reinterpret_cast<__nv_bfloat16*>(gv), nullptr, nullptr, nullptr, 3);

    k_flash_bf<<<BB*NH*18, 256, FL_SMEM>>>();

    k_gemm_bf<<<gg, 256>>>(go, gwo, attn_out_b, nullptr, out + OFF_XS, xs, router, 1);
}

// round 17
// speedup vs baseline: 1.1661x; 1.0187x over previous
#include <cuda_runtime.h>
#include <cuda_bf16.h>
#include <cuda_fp16.h>
#include <math.h>
#include <stdint.h>

#define BB 4
#define HS 48
#define CC 768
#define RR 192
#define NS 2304
#define NW 576
#define TOPK 3
#define NH 8
#define HD 96
#define NROW (BB*NS)
#define TROWS (BB*TOPK*4)
#define CROWS (BB*(NW-TOPK)*4)
#define VROW 9344

#define OFF_TP 0
#define SZ_TP  (BB*TOPK*4*CC)
#define OFF_XS (OFF_TP + SZ_TP)
#define SZ_XS  (NROW*CC)
#define OFF_ST (OFF_XS + SZ_XS)
#define SZ_ST  (3*TROWS*RR)
#define OFF_SC (OFF_ST + SZ_ST)

__device__ float g_zpart[BB*24*CC];
__device__ float g_zmean[BB*CC];
__device__ float g_zinv[BB];
__device__ float g_resp[BB*NS];
__device__ int   g_order[BB*NW];
__device__ int   g_msrc[VROW];
__device__ int   g_mtc[VROW];

__device__ float g_xr [(size_t)VROW*RR];
__device__ float g_kvrv[(size_t)VROW*3*RR];
__device__ float g_y  [(size_t)VROW*RR];
__device__ float g_o2 [(size_t)VROW*RR];
__device__ float g_tcv[(size_t)NROW*CC];

__device__ __nv_bfloat16 g_xq_b[(size_t)NROW*CC];
__device__ __nv_bfloat16 g_f_b [(size_t)NROW*CC];
__device__ __nv_bfloat16 g_q_b [(size_t)NROW*CC];
__device__ __nv_bfloat16 g_k_b [(size_t)NROW*CC];
__device__ __half        g_v_h [(size_t)NROW*CC];
__device__ __nv_bfloat16 g_o_b [(size_t)NROW*CC];
__device__ __nv_bfloat16 g_wqkv_b[3*CC*CC];
__device__ __nv_bfloat16 g_wout_b[CC*CC];

__device__ __nv_bfloat16 g_wd_h[2*RR*CC],    g_wd_l[2*RR*CC];
__device__ __nv_bfloat16 g_kvr_h[2*3*RR*RR], g_kvr_l[2*3*RR*RR];
__device__ __nv_bfloat16 g_wo_h[2*RR*RR],    g_wo_l[2*RR*RR];
__device__ __nv_bfloat16 g_wup_h[CC*RR],     g_wup_l[CC*RR];

// ------- helpers -------
__device__ __forceinline__ uint32_t smaddr(const void* p) {
    return (uint32_t)__cvta_generic_to_shared(p);
}
__device__ __forceinline__ void ldsm4(uint32_t* r, uint32_t a) {
    asm volatile("ldmatrix.sync.aligned.m8n8.x4.shared.b16 {%0,%1,%2,%3}, [%4];"
        : "=r"(r[0]), "=r"(r[1]), "=r"(r[2]), "=r"(r[3]) : "r"(a));
}
__device__ __forceinline__ void ldsm4t(uint32_t* r, uint32_t a) {
    asm volatile("ldmatrix.sync.aligned.m8n8.x4.trans.shared.b16 {%0,%1,%2,%3}, [%4];"
        : "=r"(r[0]), "=r"(r[1]), "=r"(r[2]), "=r"(r[3]) : "r"(a));
}
__device__ __forceinline__ void mma16816(float* d, const uint32_t* a, uint32_t b0, uint32_t b1) {
    asm volatile("mma.sync.aligned.m16n8k16.row.col.f32.bf16.bf16.f32 "
        "{%0,%1,%2,%3}, {%4,%5,%6,%7}, {%8,%9}, {%0,%1,%2,%3};"
        : "+f"(d[0]), "+f"(d[1]), "+f"(d[2]), "+f"(d[3])
        : "r"(a[0]), "r"(a[1]), "r"(a[2]), "r"(a[3]), "r"(b0), "r"(b1));
}
__device__ __forceinline__ void mma16816h(float* d, const uint32_t* a, uint32_t b0, uint32_t b1) {
    asm volatile("mma.sync.aligned.m16n8k16.row.col.f32.f16.f16.f32 "
        "{%0,%1,%2,%3}, {%4,%5,%6,%7}, {%8,%9}, {%0,%1,%2,%3};"
        : "+f"(d[0]), "+f"(d[1]), "+f"(d[2]), "+f"(d[3])
        : "r"(a[0]), "r"(a[1]), "r"(a[2]), "r"(a[3]), "r"(b0), "r"(b1));
}
__device__ __forceinline__ float ex2f(float x) {
    float y; asm("ex2.approx.f32 %0, %1;" : "=f"(y) : "f"(x)); return y;
}
__device__ __forceinline__ uint32_t h2ex2(uint32_t x) {
    uint32_t y; asm("ex2.approx.f16x2 %0, %1;" : "=r"(y) : "r"(x)); return y;
}
__device__ __forceinline__ uint32_t hadd2u(uint32_t a, uint32_t b) {
    uint32_t y; asm("add.rn.f16x2 %0, %1, %2;" : "=r"(y) : "r"(a), "r"(b)); return y;
}
__device__ __forceinline__ uint32_t packbf(float a, float b) {
    __nv_bfloat162 t = __floats2bfloat162_rn(a, b);
    return *reinterpret_cast<uint32_t*>(&t);
}
__device__ __forceinline__ uint32_t packh(float a, float b) {
    __half2 t = __floats2half2_rn(a, b);
    return *reinterpret_cast<uint32_t*>(&t);
}
__device__ __forceinline__ void cpasync16(uint32_t dst, const void* src) {
    asm volatile("cp.async.cg.shared.global [%0], [%1], 16;" :: "r"(dst), "l"(src));
}

// ---- K1a ----
__global__ __launch_bounds__(CC) void k_zpart(const float* __restrict__ xz) {
    int b = blockIdx.x / 24, chunk = blockIdx.x % 24;
    int c = threadIdx.x;
    const float* p = xz + ((size_t)b*NS + (size_t)chunk*96)*CC + c;
    float s = 0.f;
    #pragma unroll 4
    for (int n = 0; n < 96; n++) s += p[(size_t)n*CC];
    g_zpart[(b*24 + chunk)*CC + c] = s;
}

// ---- K1b ----
__global__ __launch_bounds__(CC) void k_zfin() {
    __shared__ float red[CC];
    int b = blockIdx.x, c = threadIdx.x;
    float s = 0.f;
    for (int j = 0; j < 24; j++) s += g_zpart[(b*24 + j)*CC + c];
    float zm = s * (1.f/NS);
    g_zmean[b*CC + c] = zm;
    red[c] = zm*zm;
    __syncthreads();
    for (int st = 512; st > 0; st >>= 1) {
        if (c < st && c + st < CC) red[c] += red[c+st];
        __syncthreads();
    }
    if (c == 0) g_zinv[b] = 1.f / fmaxf(sqrtf(red[0]), 1e-12f);
}

// ---- K2: resp ----
__global__ __launch_bounds__(256) void k_resp(const float* __restrict__ xs) {
    int row = blockIdx.x;
    int b = row / NS;
    const float* x = xs + (size_t)row*CC;
    const float* z = g_zmean + b*CC;
    float d = 0.f, xx = 0.f;
    for (int c = threadIdx.x; c < CC; c += 256) {
        float xv = x[c];
        d += xv * z[c];
        xx += xv * xv;
    }
    __shared__ float sd[8], sx2[8];
    int lane = threadIdx.x & 31, wid = threadIdx.x >> 5;
    for (int o = 16; o; o >>= 1) {
        d  += __shfl_down_sync(0xffffffffu, d, o);
        xx += __shfl_down_sync(0xffffffffu, xx, o);
    }
    if (lane == 0) { sd[wid] = d; sx2[wid] = xx; }
    __syncthreads();
    if (threadIdx.x == 0) {
        float D = 0.f, X = 0.f;
        for (int i = 0; i < 8; i++) { D += sd[i]; X += sx2[i]; }
        g_resp[row] = D * g_zinv[b] / fmaxf(sqrtf(X), 1e-12f);
    }
}

// ---- K3: window rank ----
__global__ __launch_bounds__(NW) void k_order() {
    __shared__ __align__(16) float wm[NW];
    int b = blockIdx.x, w = threadIdx.x;
    int wi = w / 24, wj = w % 24;
    int base = b*NS + (2*wi)*HS + 2*wj;
    float v = 0.25f*(g_resp[base] + g_resp[base+1] + g_resp[base+HS] + g_resp[base+HS+1]);
    wm[w] = v;
    __syncthreads();
    int rank = 0;
    const float4* wm4 = reinterpret_cast<const float4*>(wm);
    for (int j = 0; j < NW/4; j++) {
        float4 u = wm4[j];
        int j4 = 4*j;
        rank += (u.x > v || (u.x == v && j4   < w));
        rank += (u.y > v || (u.y == v && j4+1 < w));
        rank += (u.z > v || (u.z == v && j4+2 < w));
        rank += (u.w > v || (u.w == v && j4+3 < w));
    }
    g_order[b*NW + rank] = w;
}

// ---- prep ----
__global__ __launch_bounds__(256) void k_prep() {
    int vr = blockIdx.x*256 + threadIdx.x;
    if (vr >= VROW) return;
    int src = 0, tc = 0;
    bool valid = (vr < 48) || (vr >= 128 && vr < 9296);
    if (valid) {
        int b, p, t;
        if (vr < 48) { b = vr/12; int m = vr%12; p = m>>2; t = m&3; tc = b*NS + m; }
        else { int rp = vr-128; b = rp/2292; int mm = rp%2292; p = TOPK + (mm>>2); t = mm&3; tc = b*NS + 12 + mm; }
        int w = g_order[b*NW + p];
        int wi = w / 24, wj = w % 24;
        src = b*NS + (2*wi + (t>>1))*HS + 2*wj + (t&1);
    }
    g_msrc[vr] = src;
    g_mtc[vr]  = tc;
}

// ---- weight split ----
__global__ __launch_bounds__(256) void k_wsplit(
    const float* __restrict__ Wdo_w, const float* __restrict__ Wdc_w,
    const float* __restrict__ te_k, const float* __restrict__ te_v, const float* __restrict__ te_r,
    const float* __restrict__ ce_k, const float* __restrict__ ce_v, const float* __restrict__ ce_r,
    const float* __restrict__ te_o, const float* __restrict__ ce_o,
    const float* __restrict__ Wup_w)
{
    int i = blockIdx.x*256 + threadIdx.x;
    const int WD = RR*CC;
    const int WS = RR*RR;
    float v; __nv_bfloat16* hp; __nv_bfloat16* lp; int o;
    if      (i < WD)            { v = Wdo_w[i];        hp = g_wd_h;  lp = g_wd_l;  o = i; }
    else if (i < 2*WD)          { v = Wdc_w[i-WD];     hp = g_wd_h;  lp = g_wd_l;  o = i; }
    else if (i < 2*WD + WS)     { v = te_k[i-2*WD];          hp = g_kvr_h; lp = g_kvr_l; o = i-2*WD; }
    else if (i < 2*WD + 2*WS)   { v = te_v[i-2*WD-WS];       hp = g_kvr_h; lp = g_kvr_l; o = i-2*WD; }
    else if (i < 2*WD + 3*WS)   { v = te_r[i-2*WD-2*WS];     hp = g_kvr_h; lp = g_kvr_l; o = i-2*WD; }
    else if (i < 2*WD + 4*WS)   { v = ce_k[i-2*WD-3*WS];     hp = g_kvr_h; lp = g_kvr_l; o = i-2*WD; }
    else if (i < 2*WD + 5*WS)   { v = ce_v[i-2*WD-4*WS];     hp = g_kvr_h; lp = g_kvr_l; o = i-2*WD; }
    else if (i < 2*WD + 6*WS)   { v = ce_r[i-2*WD-5*WS];     hp = g_kvr_h; lp = g_kvr_l; o = i-2*WD; }
    else if (i < 2*WD + 7*WS)   { v = te_o[i-2*WD-6*WS];     hp = g_wo_h;  lp = g_wo_l;  o = i-2*WD-6*WS; }
    else if (i < 2*WD + 8*WS)   { v = ce_o[i-2*WD-7*WS];     hp = g_wo_h;  lp = g_wo_l;  o = i-2*WD-6*WS; }
    else if (i < 3*WD + 8*WS)   { v = Wup_w[i-2*WD-8*WS];    hp = g_wup_h; lp = g_wup_l; o = i-2*WD-8*WS; }
    else return;
    __nv_bfloat16 h = __float2bfloat16_rn(v);
    hp[o] = h;
    lp[o] = __float2bfloat16_rn(v - __bfloat162float(h));
}

// ---- split-precision tensor GEMM (RWKV chain) ----
#define GSTR 40
__global__ __launch_bounds__(256) void k_gemm3(
    const float* __restrict__ A, int lda, int K,
    const __nv_bfloat16* __restrict__ Bh0, const __nv_bfloat16* __restrict__ Bl0,
    const __nv_bfloat16* __restrict__ Bh1, const __nv_bfloat16* __restrict__ Bl1,
    const float* __restrict__ bias0, const float* __restrict__ bias1,
    float* __restrict__ C, int ldc, int mode, float* __restrict__ out)
{
    __shared__ __nv_bfloat16 Ah[128*GSTR], Al[128*GSTR];
    __shared__ __nv_bfloat16 Bhs[64*GSTR], Bls[64*GSTR];
    int m0 = blockIdx.x * 128, n0 = blockIdx.y * 64;
    bool e0 = (blockIdx.x == 0);
    const __nv_bfloat16* Bhp = e0 ? Bh0 : Bh1;
    const __nv_bfloat16* Blp = e0 ? Bl0 : Bl1;
    const float* bias = e0 ? bias0 : bias1;
    int tid = threadIdx.x, l = tid & 31, w = tid >> 5;
    int mw = (w >> 1) * 32, nw = (w & 1) * 32;
    int ar = tid >> 1, ac = (tid & 1) * 16;
    int br = tid >> 2, bc = (tid & 3) * 8;

    const float* Arow = A + (size_t)((mode == 0) ? g_msrc[m0+ar] : (m0+ar))*lda;

    float acc[2][4][4];
    #pragma unroll
    for (int mi = 0; mi < 2; mi++)
        #pragma unroll
        for (int nj = 0; nj < 4; nj++)
            #pragma unroll
            for (int q = 0; q < 4; q++) acc[mi][nj][q] = 0.f;

    float4 fa[4]; uint4 rbh, rbl;
    #pragma unroll
    for (int j = 0; j < 4; j++) fa[j] = *reinterpret_cast<const float4*>(Arow + ac + 4*j);
    rbh = *reinterpret_cast<const uint4*>(Bhp + (size_t)(n0+br)*K + bc);
    rbl = *reinterpret_cast<const uint4*>(Blp + (size_t)(n0+br)*K + bc);

    int g = l >> 3, lg = l & 7;
    uint32_t aoff = (uint32_t)(((mw + (l & 15))*GSTR + ((l >> 4) << 3)) * 2);
    uint32_t ah_base = smaddr(Ah) + aoff;
    uint32_t al_base = smaddr(Al) + aoff;
    uint32_t boff = (uint32_t)(((nw + ((g & 2) ? 8 : 0) + lg)*GSTR + ((g & 1) ? 8 : 0)) * 2);
    uint32_t bh_base = smaddr(Bhs) + boff;
    uint32_t bl_base = smaddr(Bls) + boff;

    for (int kc = 0; kc < K; kc += 32) {
        #pragma unroll
        for (int j = 0; j < 4; j++) {
            float vals[4] = {fa[j].x, fa[j].y, fa[j].z, fa[j].w};
            #pragma unroll
            for (int e = 0; e < 4; e += 2) {
                float v0 = vals[e], v1 = vals[e+1];
                uint32_t hp = packbf(v0, v1);
                __nv_bfloat162 hh = *reinterpret_cast<__nv_bfloat162*>(&hp);
                float l0 = v0 - __bfloat162float(hh.x);
                float l1 = v1 - __bfloat162float(hh.y);
                int col = ac + 4*j + e;
                *reinterpret_cast<uint32_t*>(&Ah[ar*GSTR + col]) = hp;
                *reinterpret_cast<uint32_t*>(&Al[ar*GSTR + col]) = packbf(l0, l1);
            }
        }
        *reinterpret_cast<uint4*>(&Bhs[br*GSTR + bc]) = rbh;
        *reinterpret_cast<uint4*>(&Bls[br*GSTR + bc]) = rbl;
        __syncthreads();
        if (kc + 32 < K) {
            #pragma unroll
            for (int j = 0; j < 4; j++)
                fa[j] = *reinterpret_cast<const float4*>(Arow + kc + 32 + ac + 4*j);
            rbh = *reinterpret_cast<const uint4*>(Bhp + (size_t)(n0+br)*K + kc + 32 + bc);
            rbl = *reinterpret_cast<const uint4*>(Blp + (size_t)(n0+br)*K + kc + 32 + bc);
        }
        #pragma unroll
        for (int kk = 0; kk < 2; kk++) {
            uint32_t ah[2][4], alr[2][4];
            ldsm4(ah[0],  ah_base + (kk*16)*2);
            ldsm4(ah[1],  ah_base + (16*GSTR + kk*16)*2);
            ldsm4(alr[0], al_base + (kk*16)*2);
            ldsm4(alr[1], al_base + (16*GSTR + kk*16)*2);
            #pragma unroll
            for (int np = 0; np < 2; np++) {
                uint32_t bh[4], bl2[4];
                ldsm4(bh,  bh_base + (np*16*GSTR + kk*16)*2);
                ldsm4(bl2, bl_base + (np*16*GSTR + kk*16)*2);
                #pragma unroll
                for (int mi = 0; mi < 2; mi++) {
                    mma16816(acc[mi][2*np],   ah[mi],  bh[0],  bh[1]);
                    mma16816(acc[mi][2*np],   ah[mi],  bl2[0], bl2[1]);
                    mma16816(acc[mi][2*np],   alr[mi], bh[0],  bh[1]);
                    mma16816(acc[mi][2*np+1], ah[mi],  bh[2],  bh[3]);
                    mma16816(acc[mi][2*np+1], ah[mi],  bl2[2], bl2[3]);
                    mma16816(acc[mi][2*np+1], alr[mi], bh[2],  bh[3]);
                }
            }
        }
        __syncthreads();
    }

    #pragma unroll
    for (int mi = 0; mi < 2; mi++) {
        int row_lo = m0 + mw + mi*16 + (l >> 2);
        #pragma unroll
        for (int nj = 0; nj < 4; nj++) {
            int col = n0 + nw + nj*8 + (l & 3)*2;
            float b0 = bias ? bias[col]   : 0.f;
            float b1 = bias ? bias[col+1] : 0.f;
            float c0 = acc[mi][nj][0] + b0, c1 = acc[mi][nj][1] + b1;
            float c2 = acc[mi][nj][2] + b0, c3 = acc[mi][nj][3] + b1;
            if (mode < 2) {
                size_t plo = (size_t)row_lo*ldc + col;
                size_t phi = (size_t)(row_lo+8)*ldc + col;
                C[plo] = c0; C[plo+1] = c1;
                C[phi] = c2; C[phi+1] = c3;
            } else {
                int vr0 = row_lo, vr1 = row_lo + 8;
                if (vr0 < 48 || (vr0 >= 128 && vr0 < 9296)) {
                    size_t p = (size_t)g_mtc[vr0]*CC + col;
                    C[p] = c0; C[p+1] = c1;
                    if (vr0 < 48) { out[OFF_TP + (size_t)vr0*CC + col] = c0; out[OFF_TP + (size_t)vr0*CC + col + 1] = c1; }
                }
                if (vr1 < 48 || (vr1 >= 128 && vr1 < 9296)) {
                    size_t p = (size_t)g_mtc[vr1]*CC + col;
                    C[p] = c2; C[p+1] = c3;
                    if (vr1 < 48) { out[OFF_TP + (size_t)vr1*CC + col] = c2; out[OFF_TP + (size_t)vr1*CC + col + 1] = c3; }
                }
            }
        }
    }
}

// ---- pointwise RWKV state update ----
__global__ __launch_bounds__(RR) void k_point(
    const float* __restrict__ state_t, const float* __restrict__ state_c,
    const float* __restrict__ te_td, const float* __restrict__ te_tf,
    const float* __restrict__ ce_td, const float* __restrict__ ce_tf,
    float* __restrict__ out)
{
    int n = threadIdx.x;
    int vr0 = blockIdx.x * 8;
    #pragma unroll
    for (int i = 0; i < 8; i++) {
        int vr = vr0 + i;
        bool top = (vr < 48);
        if (!top && (vr < 128 || vr >= 9296)) continue;
        const float* st = top ? state_t : state_c;
        int srow = top ? vr : vr - 128;
        size_t nplane = top ? (size_t)TROWS*RR : (size_t)CROWS*RR;
        float* ost = out + (top ? OFF_ST : OFF_SC);

        float kk = g_kvrv[(size_t)vr*(3*RR) + n];
        float vv = g_kvrv[(size_t)vr*(3*RR) + RR + n];
        float rr = g_kvrv[(size_t)vr*(3*RR) + 2*RR + n];
        float td = (top ? te_td : ce_td)[n];
        float tf = (top ? te_tf : ce_tf)[n];
        float wexp = expf(td);

        float rv = 1.f / (1.f + expf(-rr));
        size_t base = (size_t)srow*RR + n;
        float aa = st[base], bb = st[nplane + base], pp = st[2*nplane + base];
        float ww = tf + kk;
        float pm = fmaxf(pp, ww);
        float e1 = expf(pp - pm), e2 = expf(ww - pm);
        float wkv = (e1*aa + e2*vv) / (e1*bb + e2);
        float ww2 = pp - wexp;
        float p2 = fmaxf(ww2, kk);
        float f1 = expf(ww2 - p2), f2 = expf(kk - p2);
        ost[base]            = f1*aa + f2*vv;
        ost[nplane + base]   = f1*bb + f2;
        ost[2*nplane + base] = p2;
        g_y[(size_t)vr*RR + n] = rv * wkv;
    }
}

// ---- K5: LN -> bf16 ----
__global__ __launch_bounds__(256) void k_ln(const float* __restrict__ xs,
    const float* __restrict__ qn_g, const float* __restrict__ qn_b,
    const float* __restrict__ fn_g, const float* __restrict__ fn_b)
{
    __shared__ float row[CC];
    __shared__ float warpred[8];
    __shared__ float stat[2];
    int idx = blockIdx.x;
    bool isf = (idx >= NROW);
    int r = isf ? idx - NROW : idx;
    const float* src = isf ? g_tcv + (size_t)r*CC : xs + (size_t)r*CC;
    __nv_bfloat16* dst = isf ? g_f_b + (size_t)r*CC : g_xq_b + (size_t)r*CC;
    const float* gg = isf ? fn_g : qn_g;
    const float* bb = isf ? fn_b : qn_b;
    int tid = threadIdx.x, lane = tid & 31, wid = tid >> 5;

    float s = 0.f;
    for (int c = tid; c < CC; c += 256) { float v = src[c]; row[c] = v; s += v; }
    for (int o = 16; o; o >>= 1) s += __shfl_down_sync(0xffffffffu, s, o);
    if (lane == 0) warpred[wid] = s;
    __syncthreads();
    if (tid == 0) { float t = 0.f; for (int i = 0; i < 8; i++) t += warpred[i]; stat[0] = t * (1.f/CC); }
    __syncthreads();
    float m = stat[0], vs = 0.f;
    for (int c = tid; c < CC; c += 256) { float d = row[c] - m; vs += d*d; }
    for (int o = 16; o; o >>= 1) vs += __shfl_down_sync(0xffffffffu, vs, o);
    if (lane == 0) warpred[wid] = vs;
    __syncthreads();
    if (tid == 0) { float t = 0.f; for (int i = 0; i < 8; i++) t += warpred[i]; stat[1] = rsqrtf(t*(1.f/CC) + 1e-6f); }
    __syncthreads();
    float inv = stat[1];
    for (int c = tid; c < CC; c += 256)
        dst[c] = __float2bfloat16_rn((row[c] - m) * inv * gg[c] + bb[c]);
}

// ---- attention weight convert ----
__global__ __launch_bounds__(256) void k_wconv(const float* __restrict__ win,
                                              const float* __restrict__ wout) {
    int i = blockIdx.x*256 + threadIdx.x;
    int p = i*2;
    if (p < 3*CC*CC) {
        *reinterpret_cast<uint32_t*>(&g_wqkv_b[p]) = packbf(win[p], win[p+1]);
    }
    if (p < CC*CC) {
        *reinterpret_cast<uint32_t*>(&g_wout_b[p]) = packbf(wout[p], wout[p+1]);
    }
}

// ---- K6: bf16 tensor-core GEMM 128x64 ----
// mode 0: bf16 out. mode 1: out = xs + router*(C+bias). mode 3: fp16 out.
// mode 4: fused QKV — blockIdx.y in [0,36): e = y/12 selects {Q,K,V} operands.
#define ASTR 40
__global__ __launch_bounds__(256) void k_gemm_bf(
    const __nv_bfloat16* __restrict__ A, const __nv_bfloat16* __restrict__ W,
    const float* __restrict__ bias, __nv_bfloat16* __restrict__ dstb,
    float* __restrict__ dstf, const float* __restrict__ xs,
    const float* __restrict__ router, int mode,
    const __nv_bfloat16* __restrict__ A2,
    __nv_bfloat16* __restrict__ dstb2, __nv_bfloat16* __restrict__ dstb3)
{
    __shared__ __nv_bfloat16 As[128*ASTR];
    __shared__ __nv_bfloat16 Bs[64*ASTR];
    int m0 = blockIdx.x * 128;
    int n0, emode;
    if (mode == 4) {
        int e = blockIdx.y / 12;
        n0 = (blockIdx.y % 12) * 64;
        A = (e == 0) ? A : A2;
        W = W + (size_t)e*CC*CC;
        bias = bias + e*CC;
        dstb = (e == 0) ? dstb : (e == 1 ? dstb2 : dstb3);
        emode = (e == 2) ? 3 : 0;
    } else {
        n0 = blockIdx.y * 64;
        emode = mode;
    }
    int tid = threadIdx.x;
    int l = tid & 31, w = tid >> 5;
    int mw = (w >> 1) * 32, nw = (w & 1) * 32;
    int ldr = tid >> 2, ldc = (tid & 3) * 8;

    float acc[2][4][4];
    #pragma unroll
    for (int mi = 0; mi < 2; mi++)
        #pragma unroll
        for (int nj = 0; nj < 4; nj++)
            #pragma unroll
            for (int q = 0; q < 4; q++) acc[mi][nj][q] = 0.f;

    uint4 ra0, ra1, rb;
    ra0 = *reinterpret_cast<const uint4*>(A + (size_t)(m0+ldr)*CC + ldc);
    ra1 = *reinterpret_cast<const uint4*>(A + (size_t)(m0+64+ldr)*CC + ldc);
    rb  = *reinterpret_cast<const uint4*>(W + (size_t)(n0+ldr)*CC + ldc);

    int g = l >> 3, lg = l & 7;
    uint32_t a_base = smaddr(As) + (uint32_t)(((mw + (l & 15))*ASTR + ((l >> 4) << 3)) * 2);
    uint32_t b_base = smaddr(Bs) + (uint32_t)(((nw + ((g & 2) ? 8 : 0) + lg)*ASTR + ((g & 1) ? 8 : 0)) * 2);

    for (int kc = 0; kc < CC; kc += 32) {
        *reinterpret_cast<uint4*>(&As[ldr*ASTR + ldc])      = ra0;
        *reinterpret_cast<uint4*>(&As[(64+ldr)*ASTR + ldc]) = ra1;
        *reinterpret_cast<uint4*>(&Bs[ldr*ASTR + ldc])      = rb;
        __syncthreads();
        if (kc + 32 < CC) {
            ra0 = *reinterpret_cast<const uint4*>(A + (size_t)(m0+ldr)*CC + kc + 32 + ldc);
            ra1 = *reinterpret_cast<const uint4*>(A + (size_t)(m0+64+ldr)*CC + kc + 32 + ldc);
            rb  = *reinterpret_cast<const uint4*>(W + (size_t)(n0+ldr)*CC + kc + 32 + ldc);
        }
        #pragma unroll
        for (int kk = 0; kk < 2; kk++) {
            uint32_t af[2][4];
            ldsm4(af[0], a_base + (kk*16)*2);
            ldsm4(af[1], a_base + (16*ASTR + kk*16)*2);
            #pragma unroll
            for (int np = 0; np < 2; np++) {
                uint32_t bf[4];
                ldsm4(bf, b_base + (np*16*ASTR + kk*16)*2);
                #pragma unroll
                for (int mi = 0; mi < 2; mi++) {
                    mma16816(acc[mi][2*np],   af[mi], bf[0], bf[1]);
                    mma16816(acc[mi][2*np+1], af[mi], bf[2], bf[3]);
                }
            }
        }
        __syncthreads();
    }

    #pragma unroll
    for (int mi = 0; mi < 2; mi++) {
        int row_lo = m0 + mw + mi*16 + (l >> 2);
        #pragma unroll
        for (int nj = 0; nj < 4; nj++) {
            int col = n0 + nw + nj*8 + (l & 3)*2;
            float b0 = bias[col], b1 = bias[col+1];
            float c0 = acc[mi][nj][0] + b0, c1 = acc[mi][nj][1] + b1;
            float c2 = acc[mi][nj][2] + b0, c3 = acc[mi][nj][3] + b1;
            size_t plo = (size_t)row_lo*CC + col;
            size_t phi = (size_t)(row_lo+8)*CC + col;
            if (emode == 0) {
                *reinterpret_cast<uint32_t*>(&dstb[plo]) = packbf(c0, c1);
                *reinterpret_cast<uint32_t*>(&dstb[phi]) = packbf(c2, c3);
            } else if (emode == 3) {
                __half* dh = reinterpret_cast<__half*>(dstb);
                *reinterpret_cast<uint32_t*>(&dh[plo]) = packh(c0, c1);
                *reinterpret_cast<uint32_t*>(&dh[phi]) = packh(c2, c3);
            } else {
                float r0 = router[col], r1 = router[col+1];
                dstf[plo]   = xs[plo]   + r0*c0;
                dstf[plo+1] = xs[plo+1] + r1*c1;
                dstf[phi]   = xs[phi]   + r0*c2;
                dstf[phi+1] = xs[phi+1] + r1*c3;
            }
        }
    }
}

// ---- K7: flash attention — 3-stage cp.async KV pipeline, Q frags in regs ----
#define QSTR 104
#define STG  (2*64*QSTR)
#define FL_Q  0
#define FL_KV (128*QSTR)
#define FL_SMEM ((FL_KV + 3*STG)*2)

__global__ __launch_bounds__(256) void k_flash_bf() {
    extern __shared__ __align__(16) __nv_bfloat16 fsm[];
    __nv_bfloat16* Qs = fsm + FL_Q;

    int blk = blockIdx.x;
    int qt = blk % 18;
    int h  = (blk / 18) % NH;
    int b  = blk / (18*NH);
    int q0 = qt * 128;
    int tid = threadIdx.x;
    int l = tid & 31, w = tid >> 5;
    int g = l >> 3, lg = l & 7;
    const float sc2 = 0.14725602686637387f;

    int cr[3], cj[3];
    #pragma unroll
    for (int c = 0; c < 3; c++) { int i = tid + c*256; cr[c] = i / 12; cj[c] = (i % 12) * 8; }
    uint32_t kv_s = smaddr(fsm) + FL_KV*2;
    const size_t hbase = (size_t)(b*NS)*CC + h*HD;

    #pragma unroll
    for (int s = 0; s < 2; s++) {
        int k0 = s * 64;
        uint32_t sb = kv_s + s*STG*2;
        #pragma unroll
        for (int c = 0; c < 3; c++) {
            cpasync16(sb + (cr[c]*QSTR + cj[c])*2,            &g_k_b[hbase + (size_t)(k0 + cr[c])*CC + cj[c]]);
            cpasync16(sb + ((64 + cr[c])*QSTR + cj[c])*2,     &g_v_h[hbase + (size_t)(k0 + cr[c])*CC + cj[c]]);
        }
        asm volatile("cp.async.commit_group;");
    }

    for (int i = tid; i < 128*12; i += 256) {
        int r = i / 12, j = i % 12;
        *reinterpret_cast<uint4*>(&Qs[r*QSTR + j*8]) =
            *reinterpret_cast<const uint4*>(&g_q_b[hbase + (size_t)(q0 + r)*CC + j*8]);
    }
    __syncthreads();

    uint32_t q_base = smaddr(Qs) + (uint32_t)(((w*16 + (l & 15))*QSTR + ((l >> 4) << 3)) * 2);
    uint32_t qf[6][4];
    #pragma unroll
    for (int d = 0; d < 6; d++) ldsm4(qf[d], q_base + (d*16)*2);

    uint32_t k_lane = (uint32_t)(((((g & 2) ? 8 : 0) + lg)*QSTR + ((g & 1) ? 8 : 0)) * 2);
    uint32_t v_lane = (uint32_t)((((64 + ((g & 1) ? 8 : 0) + lg))*QSTR + ((g & 2) ? 8 : 0)) * 2);

    float Oacc[12][4];
    float m_lo = -1e30f, m_hi = -1e30f, l_lo = 0.f, l_hi = 0.f;
    #pragma unroll
    for (int t = 0; t < 12; t++)
        #pragma unroll
        for (int q = 0; q < 4; q++) Oacc[t][q] = 0.f;

    for (int kt = 0; kt < 36; kt++) {
        if (kt < 35) asm volatile("cp.async.wait_group 1;" ::: "memory");
        else         asm volatile("cp.async.wait_group 0;" ::: "memory");
        __syncthreads();

        if (kt + 2 < 36) {
            int k0n = (kt + 2) * 64;
            uint32_t sb = kv_s + ((kt + 2) % 3)*STG*2;
            #pragma unroll
            for (int c = 0; c < 3; c++) {
                cpasync16(sb + (cr[c]*QSTR + cj[c])*2,        &g_k_b[hbase + (size_t)(k0n + cr[c])*CC + cj[c]]);
                cpasync16(sb + ((64 + cr[c])*QSTR + cj[c])*2, &g_v_h[hbase + (size_t)(k0n + cr[c])*CC + cj[c]]);
            }
            asm volatile("cp.async.commit_group;");
        }

        uint32_t stage = kv_s + (kt % 3)*STG*2;
        uint32_t k_base = stage + k_lane;
        uint32_t v_base = stage + v_lane;

        float sacc[8][4];
        #pragma unroll
        for (int j = 0; j < 8; j++)
            #pragma unroll
            for (int q = 0; q < 4; q++) sacc[j][q] = 0.f;
        #pragma unroll
        for (int d = 0; d < 6; d++) {
            #pragma unroll
            for (int np = 0; np < 4; np++) {
                uint32_t bf[4];
                ldsm4(bf, k_base + (np*16*QSTR + d*16)*2);
                mma16816(sacc[2*np],   qf[d], bf[0], bf[1]);
                mma16816(sacc[2*np+1], qf[d], bf[2], bf[3]);
            }
        }

        float mx_lo = -1e30f, mx_hi = -1e30f;
        #pragma unroll
        for (int j = 0; j < 8; j++) {
            mx_lo = fmaxf(mx_lo, fmaxf(sacc[j][0], sacc[j][1]));
            mx_hi = fmaxf(mx_hi, fmaxf(sacc[j][2], sacc[j][3]));
        }
        mx_lo *= sc2; mx_hi *= sc2;
        mx_lo = fmaxf(mx_lo, __shfl_xor_sync(0xffffffffu, mx_lo, 1));
        mx_lo = fmaxf(mx_lo, __shfl_xor_sync(0xffffffffu, mx_lo, 2));
        mx_hi = fmaxf(mx_hi, __shfl_xor_sync(0xffffffffu, mx_hi, 1));
        mx_hi = fmaxf(mx_hi, __shfl_xor_sync(0xffffffffu, mx_hi, 2));
        float mn_lo = fmaxf(m_lo, mx_lo), mn_hi = fmaxf(m_hi, mx_hi);
        float al_lo = ex2f(m_lo - mn_lo), al_hi = ex2f(m_hi - mn_hi);

        uint32_t ph[8][2];
        #pragma unroll
        for (int j = 0; j < 8; j++) {
            float x0 = fmaf(sacc[j][0], sc2, -mn_lo);
            float x1 = fmaf(sacc[j][1], sc2, -mn_lo);
            float x2 = fmaf(sacc[j][2], sc2, -mn_hi);
            float x3 = fmaf(sacc[j][3], sc2, -mn_hi);
            ph[j][0] = h2ex2(packh(x0, x1));
            ph[j][1] = h2ex2(packh(x2, x3));
        }
        uint32_t slo = hadd2u(hadd2u(hadd2u(ph[0][0], ph[1][0]), hadd2u(ph[2][0], ph[3][0])),
                              hadd2u(hadd2u(ph[4][0], ph[5][0]), hadd2u(ph[6][0], ph[7][0])));
        uint32_t shi = hadd2u(hadd2u(hadd2u(ph[0][1], ph[1][1]), hadd2u(ph[2][1], ph[3][1])),
                              hadd2u(hadd2u(ph[4][1], ph[5][1]), hadd2u(ph[6][1], ph[7][1])));
        __half2 hlo = *reinterpret_cast<__half2*>(&slo);
        __half2 hhi = *reinterpret_cast<__half2*>(&shi);
        float rs_lo = __low2float(hlo) + __high2float(hlo);
        float rs_hi = __low2float(hhi) + __high2float(hhi);
        rs_lo += __shfl_xor_sync(0xffffffffu, rs_lo, 1);
        rs_lo += __shfl_xor_sync(0xffffffffu, rs_lo, 2);
        rs_hi += __shfl_xor_sync(0xffffffffu, rs_hi, 1);
        rs_hi += __shfl_xor_sync(0xffffffffu, rs_hi, 2);
        l_lo = l_lo*al_lo + rs_lo;
        l_hi = l_hi*al_hi + rs_hi;
        m_lo = mn_lo; m_hi = mn_hi;
        #pragma unroll
        for (int t = 0; t < 12; t++) {
            Oacc[t][0] *= al_lo; Oacc[t][1] *= al_lo;
            Oacc[t][2] *= al_hi; Oacc[t][3] *= al_hi;
        }

        #pragma unroll
        for (int kt2 = 0; kt2 < 4; kt2++) {
            uint32_t pf[4];
            pf[0] = ph[2*kt2][0];
            pf[1] = ph[2*kt2][1];
            pf[2] = ph[2*kt2+1][0];
            pf[3] = ph[2*kt2+1][1];
            #pragma unroll
            for (int dp = 0; dp < 6; dp++) {
                uint32_t vf[4];
                ldsm4t(vf, v_base + (kt2*16*QSTR + dp*16)*2);
                mma16816h(Oacc[2*dp],   pf, vf[0], vf[1]);
                mma16816h(Oacc[2*dp+1], pf, vf[2], vf[3]);
            }
        }
    }

    float inv_lo = 1.f / l_lo, inv_hi = 1.f / l_hi;
    int row_lo = b*NS + q0 + w*16 + (l >> 2);
    #pragma unroll
    for (int t = 0; t < 12; t++) {
        int col = h*HD + t*8 + (l & 3)*2;
        *reinterpret_cast<uint32_t*>(&g_o_b[(size_t)row_lo*CC + col]) =
            packbf(Oacc[t][0]*inv_lo, Oacc[t][1]*inv_lo);
        *reinterpret_cast<uint32_t*>(&g_o_b[(size_t)(row_lo+8)*CC + col]) =
            packbf(Oacc[t][2]*inv_hi, Oacc[t][3]*inv_hi);
    }
}

extern "C" void kernel_launch(void* const* d_in, const int* in_sizes, int n_in,
                              void* d_out, int out_size) {
    const float* xz       = (const float*)d_in[0];
    const float* xs       = (const float*)d_in[1];
    const float* state_t  = (const float*)d_in[2];
    const float* state_c  = (const float*)d_in[3];
    const float* Wdo_w    = (const float*)d_in[4];
    const float* Wdo_b    = (const float*)d_in[5];
    const float* Wdc_w    = (const float*)d_in[6];
    const float* Wdc_b    = (const float*)d_in[7];
    const float* Wup_w    = (const float*)d_in[8];
    const float* Wup_b    = (const float*)d_in[9];
    const float* te_td    = (const float*)d_in[10];
    const float* te_tf    = (const float*)d_in[11];
    const float* te_k     = (const float*)d_in[12];
    const float* te_v     = (const float*)d_in[13];
    const float* te_r     = (const float*)d_in[14];
    const float* te_o     = (const float*)d_in[15];
    const float* ce_td    = (const float*)d_in[16];
    const float* ce_tf    = (const float*)d_in[17];
    const float* ce_k     = (const float*)d_in[18];
    const float* ce_v     = (const float*)d_in[19];
    const float* ce_r     = (const float*)d_in[20];
    const float* ce_o     = (const float*)d_in[21];
    const float* qn_g     = (const float*)d_in[22];
    const float* qn_b     = (const float*)d_in[23];
    const float* fn_g     = (const float*)d_in[24];
    const float* fn_b     = (const float*)d_in[25];
    const float* attn_in_w  = (const float*)d_in[26];
    const float* attn_in_b  = (const float*)d_in[27];
    const float* attn_out_w = (const float*)d_in[28];
    const float* attn_out_b = (const float*)d_in[29];
    const float* router     = (const float*)d_in[30];
    float* out = (float*)d_out;

    cudaFuncSetAttribute(k_flash_bf, cudaFuncAttributeMaxDynamicSharedMemorySize, FL_SMEM);

    __nv_bfloat16 *gxq, *gf, *gq, *gk, *go, *gwq, *gwo;
    __half *gv;
    cudaGetSymbolAddress((void**)&gxq, g_xq_b);
    cudaGetSymbolAddress((void**)&gf,  g_f_b);
    cudaGetSymbolAddress((void**)&gq,  g_q_b);
    cudaGetSymbolAddress((void**)&gk,  g_k_b);
    cudaGetSymbolAddress((void**)&gv,  g_v_h);
    cudaGetSymbolAddress((void**)&go,  g_o_b);
    cudaGetSymbolAddress((void**)&gwq, g_wqkv_b);
    cudaGetSymbolAddress((void**)&gwo, g_wout_b);

    float *gxr, *gkvrv, *gy, *go2, *gtcv;
    cudaGetSymbolAddress((void**)&gxr,   g_xr);
    cudaGetSymbolAddress((void**)&gkvrv, g_kvrv);
    cudaGetSymbolAddress((void**)&gy,    g_y);
    cudaGetSymbolAddress((void**)&go2,   g_o2);
    cudaGetSymbolAddress((void**)&gtcv,  g_tcv);

    __nv_bfloat16 *wdh, *wdl, *kvh, *kvl, *woh, *wol, *wuh, *wul;
    cudaGetSymbolAddress((void**)&wdh, g_wd_h);
    cudaGetSymbolAddress((void**)&wdl, g_wd_l);
    cudaGetSymbolAddress((void**)&kvh, g_kvr_h);
    cudaGetSymbolAddress((void**)&kvl, g_kvr_l);
    cudaGetSymbolAddress((void**)&woh, g_wo_h);
    cudaGetSymbolAddress((void**)&wol, g_wo_l);
    cudaGetSymbolAddress((void**)&wuh, g_wup_h);
    cudaGetSymbolAddress((void**)&wul, g_wup_l);

    const int WD = RR*CC, WS = RR*RR;
    const int WSPLIT_N = 3*WD + 8*WS;

    k_zpart<<<BB*24, CC>>>(xz);
    k_zfin<<<BB, CC>>>();
    k_resp<<<NROW, 256>>>(xs);
    k_order<<<BB, NW>>>();
    k_prep<<<(VROW + 255)/256, 256>>>();
    k_wsplit<<<(WSPLIT_N + 255)/256, 256>>>(Wdo_w, Wdc_w, te_k, te_v, te_r,
                                            ce_k, ce_v, ce_r, te_o, ce_o, Wup_w);
    k_wconv<<<(3*CC*CC/2 + 255)/256, 256>>>(attn_in_w, attn_out_w);

    // RWKV dense chain on tensor cores
    k_gemm3<<<dim3(VROW/128, RR/64), 256>>>(xs, CC, CC,
        wdh, wdl, wdh + WD, wdl + WD, Wdo_b, Wdc_b, gxr, RR, 0, nullptr);
    k_gemm3<<<dim3(VROW/128, 3*RR/64), 256>>>(gxr, RR, RR,
        kvh, kvl, kvh + 3*WS, kvl + 3*WS, nullptr, nullptr, gkvrv, 3*RR, 1, nullptr);
    k_point<<<VROW/8, RR>>>(state_t, state_c, te_td, te_tf, ce_td, ce_tf, out);
    k_gemm3<<<dim3(VROW/128, RR/64), 256>>>(gy, RR, RR,
        woh, wol, woh + WS, wol + WS, nullptr, nullptr, go2, RR, 1, nullptr);
    k_gemm3<<<dim3(VROW/128, CC/64), 256>>>(go2, RR, RR,
        wuh, wul, wuh, wul, Wup_b, Wup_b, gtcv, CC, 2, out);

    k_ln<<<2*NROW, 256>>>(xs, qn_g, qn_b, fn_g, fn_b);

    // fused QKV GEMM: one launch, 36 y-tiles (12 Q, 12 K, 12 V)
    k_gemm_bf<<<dim3(NROW/128, 36), 256>>>(gxq, gwq, attn_in_b,
        gq, nullptr, nullptr, nullptr, 4,
        gf, gk, reinterpret_cast<__nv_bfloat16*>(gv));

    k_flash_bf<<<BB*NH*18, 256, FL_SMEM>>>();

    k_gemm_bf<<<dim3(NROW/128, CC/64), 256>>>(go, gwo, attn_out_b,
        nullptr, out + OFF_XS, xs, router, 1,
        nullptr, nullptr, nullptr);
}